// round 6
// baseline (speedup 1.0000x reference)
#include <cuda_runtime.h>
#include <math.h>
#include <stdint.h>

#define S_LEN 512

typedef unsigned long long u64;

__device__ __forceinline__ void fma2(u64 &d, u64 a, u64 b) {
    asm("fma.rn.f32x2 %0, %1, %2, %3;" : "=l"(d) : "l"(a), "l"(b), "l"(d));
}
__device__ __forceinline__ float lo32(u64 v) { return __uint_as_float((unsigned)(v & 0xffffffffULL)); }
__device__ __forceinline__ float hi32(u64 v) { return __uint_as_float((unsigned)(v >> 32)); }

// ---------------- static scratch (no allocations allowed) ----------------
__device__ float g_xg  [16384 * 3072];  // input-projection output, reused per layer
__device__ float g_bufA[16384 * 512];   // layer0 out, later layer2 out
__device__ float g_bufB[16384 * 1024];  // layer1 out
__device__ float g_h   [32 * 1024];     // hidden state, packed [k/2][b][2]
__device__ float g_rh  [32 * 1024];     // r*h, same packing

__device__ unsigned          g_bar_cnt    = 0;
__device__ volatile unsigned g_bar_epoch  = 0;
__device__ volatile unsigned g_bar_broken = 0;

__device__ __forceinline__ const float* sel_in(const float* ext, int sel) {
    return sel == 0 ? g_bufA : (sel == 1 ? g_bufB : ext);
}
__device__ __forceinline__ float* sel_out(float* ext, int sel) {
    return sel == 0 ? g_bufA : (sel == 1 ? g_bufB : (sel == 2 ? g_xg : ext));
}

// Software grid barrier. All NC CTAs are co-resident: SMEM >= 112KB forces
// 1 CTA/SM and classic launch places the first 148 CTAs on distinct SMs
// (NC <= 128). Counter self-resets each barrier; epoch is monotonic (persists
// across launches/replays; wrap-safe). Escape hatch: a waiter spinning longer
// than ~0.3s declares the barrier broken; every later barrier falls through,
// producing a fast wrong answer (visible as rel_err) instead of a 600s hang.
__device__ __forceinline__ void grid_barrier(unsigned NC) {
    __syncthreads();
    if (threadIdx.x == 0) {
        if (!g_bar_broken) {
            __threadfence();
            unsigned e = g_bar_epoch;
            if (atomicAdd(&g_bar_cnt, 1u) == NC - 1u) {
                g_bar_cnt = 0u;
                __threadfence();
                g_bar_epoch = e + 1u;
            } else {
                unsigned long long t0 = clock64();
                while (g_bar_epoch == e && !g_bar_broken) {
                    __nanosleep(64);
                    if (clock64() - t0 > 400000000ULL) { g_bar_broken = 1u; break; }
                }
            }
            __threadfence();
        }
    }
    __syncthreads();
}

// ---------------- GRU recurrence: persistent column-parallel scan ----------------
// One launch per layer. Each CTA owns 8 hidden columns (1 per warp); its Wh row
// slices stay in SMEM for the whole scan. Lanes = batch (B=32 = warp width).
// Per step: stage full h from L2; phase A computes r,z and publishes r*h;
// grid barrier; stage r*h; phase B computes n, updates h, writes ys; barrier.
// h/rh are packed pair-major [k/2][b][2] so each lane loads one u64 per k-pair
// and dot products run on packed fma.rn.f32x2 (2x scalar FFMA rate).
__global__ void __launch_bounds__(256, 1) gru_scan_kernel(
    const float* __restrict__ Wh,   // [3H, H]
    const float* __restrict__ h0,   // [H]
    int H, int NC, int ysel)
{
    extern __shared__ float smem[];
    const int H2 = H >> 1;
    float* wA   = smem;              // [H2][8 cols][4]: (Wr[2k],Wr[2k+1],Wz[2k],Wz[2k+1])
    float* wN   = wA + H * 16;       // [H2][8 cols][2]: (Wn[2k],Wn[2k+1])
    float* hbuf = wN + H * 8;        // [H2][32][2]: staged h (A) / r*h (B)

    const int tid = threadIdx.x;
    const int w   = tid >> 5;        // warp = column within CTA
    const int l   = tid & 31;        // lane = batch element
    const int c0  = blockIdx.x * 8;
    const int c   = c0 + w;
    const int G3  = 3 * H;

    if (tid == 0) g_bar_broken = 0;  // benign multi-writer reset, pre-first-barrier

    // Stage weights once for the whole scan (coalesced global reads).
    for (int j = 0; j < 8; ++j) {
        const float* wr = Wh + (size_t)(c0 + j) * H;
        const float* wz = Wh + (size_t)(H + c0 + j) * H;
        const float* wn = Wh + (size_t)(2 * H + c0 + j) * H;
        for (int k2 = tid; k2 < H2; k2 += 256) {
            wA[k2 * 32 + j * 4 + 0] = wr[2 * k2];
            wA[k2 * 32 + j * 4 + 1] = wr[2 * k2 + 1];
            wA[k2 * 32 + j * 4 + 2] = wz[2 * k2];
            wA[k2 * 32 + j * 4 + 3] = wz[2 * k2 + 1];
            wN[k2 * 16 + j * 2 + 0] = wn[2 * k2];
            wN[k2 * 16 + j * 2 + 1] = wn[2 * k2 + 1];
        }
    }

    float hreg = h0[c];                                    // h[c] for every batch lane
    __stcg(&g_h[(c >> 1) * 64 + l * 2 + (c & 1)], hreg);
    grid_barrier(NC);

    float* ys = (ysel == 1) ? g_bufB : g_bufA;
    const int nv4 = H * 8;                                 // float4 count of 32*H floats
    const u64*        hb  = (const u64*)hbuf;
    const ulonglong2* wa  = (const ulonglong2*)wA;
    const u64*        wn2 = (const u64*)wN;

    for (int s = 0; s < S_LEN; ++s) {
        // stage full h (L2-coherent)
        {
            const float4* src = (const float4*)g_h;
            float4*       dst = (float4*)hbuf;
            for (int i = tid; i < nv4; i += 256) dst[i] = __ldcg(src + i);
        }
        __syncthreads();

        const int xbase = (l * S_LEN + s) * G3 + c;
        float xr = __ldg(&g_xg[xbase]);
        float xz = __ldg(&g_xg[xbase + H]);

        // phase A: r, z
        u64 accR = 0, accZ = 0;
        #pragma unroll 8
        for (int k2 = 0; k2 < H2; ++k2) {
            u64 h2 = hb[k2 * 32 + l];            // (h[2k2],h[2k2+1]) for batch l
            ulonglong2 wv = wa[k2 * 8 + w];      // broadcast: r-pair, z-pair
            fma2(accR, h2, wv.x);
            fma2(accZ, h2, wv.y);
        }
        float r = 1.0f / (1.0f + expf(-(xr + lo32(accR) + hi32(accR))));
        float z = 1.0f / (1.0f + expf(-(xz + lo32(accZ) + hi32(accZ))));
        __stcg(&g_rh[(c >> 1) * 64 + l * 2 + (c & 1)], r * hreg);

        grid_barrier(NC);                        // all r*h published

        // stage full r*h
        {
            const float4* src = (const float4*)g_rh;
            float4*       dst = (float4*)hbuf;
            for (int i = tid; i < nv4; i += 256) dst[i] = __ldcg(src + i);
        }
        __syncthreads();

        // phase B: n, h update
        float xn = __ldg(&g_xg[xbase + 2 * H]);
        u64 accN = 0;
        #pragma unroll 8
        for (int k2 = 0; k2 < H2; ++k2) {
            u64 h2 = hb[k2 * 32 + l];
            fma2(accN, h2, wn2[k2 * 8 + w]);
        }
        float n = tanhf(xn + lo32(accN) + hi32(accN));
        float hnew = (1.0f - z) * hreg + z * n;  // nonstandard z convention (matches ref)
        hreg = hnew;
        __stcg(&g_h[(c >> 1) * 64 + l * 2 + (c & 1)], hnew);
        ys[(size_t)(l * S_LEN + s) * H + c] = hnew;

        grid_barrier(NC);                        // h complete before next staging
    }
}

// ---------------- fp32 GEMM: C[M,N] = A[M,K] @ W[N,K]^T + bias (+ReLU) ----------------
// Identical to the round-5 kernel that passed correctness.
template <bool RELU>
__global__ void __launch_bounds__(256) gemm_kernel(
    const float* __restrict__ Aext, int asel,
    const float* __restrict__ W, const float* __restrict__ bias,
    float* __restrict__ Cext, int csel,
    int M, int N, int K)
{
    const float* A = sel_in(Aext, asel);
    float*       C = sel_out(Cext, csel);

    __shared__ float As[16][128];   // [k][m]
    __shared__ float Bs[16][128];   // [k][n]

    const int tid = threadIdx.x;
    const int m0  = blockIdx.y * 128;
    const int n0  = blockIdx.x * 128;
    const int tym = tid >> 4;        // 0..15 -> 8 rows each
    const int txn = tid & 15;        // 0..15 -> 8 cols each
    const int row = tid >> 1;        // 0..127 tile row for loads
    const int kh  = (tid & 1) * 8;   // k-half for loads

    float acc[8][8];
    #pragma unroll
    for (int i = 0; i < 8; ++i)
        #pragma unroll
        for (int j = 0; j < 8; ++j) acc[i][j] = 0.0f;

    const float* Aptr = A + (size_t)(m0 + row) * K + kh;
    const float* Wptr = W + (size_t)(n0 + row) * K + kh;

    for (int k0 = 0; k0 < K; k0 += 16) {
        float4 a0 = *(const float4*)(Aptr + k0);
        float4 a1 = *(const float4*)(Aptr + k0 + 4);
        float4 b0 = *(const float4*)(Wptr + k0);
        float4 b1 = *(const float4*)(Wptr + k0 + 4);
        __syncthreads();
        float va[8] = {a0.x, a0.y, a0.z, a0.w, a1.x, a1.y, a1.z, a1.w};
        float vb[8] = {b0.x, b0.y, b0.z, b0.w, b1.x, b1.y, b1.z, b1.w};
        #pragma unroll
        for (int i = 0; i < 8; ++i) {
            As[kh + i][row] = va[i];
            Bs[kh + i][row] = vb[i];
        }
        __syncthreads();
        #pragma unroll
        for (int k = 0; k < 16; ++k) {
            float a[8], b[8];
            *(float4*)(a)     = *(const float4*)&As[k][tym * 8];
            *(float4*)(a + 4) = *(const float4*)&As[k][tym * 8 + 4];
            *(float4*)(b)     = *(const float4*)&Bs[k][txn * 8];
            *(float4*)(b + 4) = *(const float4*)&Bs[k][txn * 8 + 4];
            #pragma unroll
            for (int i = 0; i < 8; ++i)
                #pragma unroll
                for (int j = 0; j < 8; ++j)
                    acc[i][j] = fmaf(a[i], b[j], acc[i][j]);
        }
    }

    const int mBase = m0 + tym * 8;
    const int nBase = n0 + txn * 8;
    #pragma unroll
    for (int i = 0; i < 8; ++i) {
        float* crow = C + (size_t)(mBase + i) * N + nBase;
        #pragma unroll
        for (int j = 0; j < 8; ++j) {
            float v = acc[i][j] + bias[nBase + j];
            if (RELU) v = fmaxf(v, 0.0f);
            crow[j] = v;
        }
    }
}

// ---------------- host ----------------
extern "C" void kernel_launch(void* const* d_in, const int* in_sizes, int n_in,
                              void* d_out, int out_size) {
    (void)in_sizes; (void)n_in; (void)out_size;
    const float* x   = (const float*)d_in[0];
    const float* Wi0 = (const float*)d_in[1];
    const float* Wh0 = (const float*)d_in[2];
    const float* bh0 = (const float*)d_in[3];
    const float* h00 = (const float*)d_in[4];
    const float* Wi1 = (const float*)d_in[5];
    const float* Wh1 = (const float*)d_in[6];
    const float* bh1 = (const float*)d_in[7];
    const float* h01 = (const float*)d_in[8];
    const float* Wi2 = (const float*)d_in[9];
    const float* Wh2 = (const float*)d_in[10];
    const float* bh2 = (const float*)d_in[11];
    const float* h02 = (const float*)d_in[12];
    const float* Wo  = (const float*)d_in[13];
    const float* bo  = (const float*)d_in[14];
    float* out = (float*)d_out;

    // scan SMEM: 56*H floats (wA 16H + wN 8H + hbuf 32H); H=1024 -> 224 KB
    cudaFuncSetAttribute(gru_scan_kernel,
                         cudaFuncAttributeMaxDynamicSharedMemorySize, 229376);

    const int M = 16384;
    dim3 blk(256);

    // ---- layer 0: I=256, H=512 ----
    gemm_kernel<false><<<dim3(12, 128), blk>>>(x, 3, Wi0, bh0, nullptr, 2, M, 1536, 256);
    gru_scan_kernel<<<64, blk, 56 * 512 * 4>>>(Wh0, h00, 512, 64, 0);
    // ---- layer 1: I=512, H=1024 ----
    gemm_kernel<false><<<dim3(24, 128), blk>>>(nullptr, 0, Wi1, bh1, nullptr, 2, M, 3072, 512);
    gru_scan_kernel<<<128, blk, 56 * 1024 * 4>>>(Wh1, h01, 1024, 128, 1);
    // ---- layer 2: I=1024, H=512 ----
    gemm_kernel<false><<<dim3(12, 128), blk>>>(nullptr, 1, Wi2, bh2, nullptr, 2, M, 1536, 1024);
    gru_scan_kernel<<<64, blk, 56 * 512 * 4>>>(Wh2, h02, 512, 64, 0);
    // ---- output head: [16384,512] @ Wo^T -> [16384,256], ReLU ----
    gemm_kernel<true><<<dim3(2, 128), blk>>>(nullptr, 0, Wo, bo, out, 3, M, 256, 512);
}

// round 7
// speedup vs baseline: 1.2727x; 1.2727x over previous
#include <cuda_runtime.h>
#include <math.h>
#include <stdint.h>

#define S_LEN 512

typedef unsigned long long u64;

__device__ __forceinline__ void fma2(u64 &d, u64 a, u64 b) {
    asm("fma.rn.f32x2 %0, %1, %2, %3;" : "=l"(d) : "l"(a), "l"(b), "l"(d));
}
__device__ __forceinline__ void add2(u64 &d, u64 a, u64 b) {
    asm("add.rn.f32x2 %0, %1, %2;" : "=l"(d) : "l"(a), "l"(b));
}
__device__ __forceinline__ float lo32(u64 v) { return __uint_as_float((unsigned)(v & 0xffffffffULL)); }
__device__ __forceinline__ float hi32(u64 v) { return __uint_as_float((unsigned)(v >> 32)); }

// ---------------- static scratch (no allocations allowed) ----------------
__device__ float g_xg  [16384 * 3072];  // input-projection output, reused per layer
__device__ float g_bufA[16384 * 512];   // layer0 out, later layer2 out
__device__ float g_bufB[16384 * 1024];  // layer1 out
__device__ float g_h   [32 * 1024];     // hidden state, packed [k/2][b][2]
__device__ float g_rh  [32 * 1024];     // r*h, same packing

__device__ unsigned          g_bar_cnt    = 0;
__device__ volatile unsigned g_bar_epoch  = 0;
__device__ volatile unsigned g_bar_broken = 0;

__device__ __forceinline__ const float* sel_in(const float* ext, int sel) {
    return sel == 0 ? g_bufA : (sel == 1 ? g_bufB : ext);
}
__device__ __forceinline__ float* sel_out(float* ext, int sel) {
    return sel == 0 ? g_bufA : (sel == 1 ? g_bufB : (sel == 2 ? g_xg : ext));
}

// Software grid barrier (validated in round 6). All NC CTAs co-resident.
// Escape hatch: a waiter spinning > ~0.2s marks the barrier broken; later
// barriers fall through -> fast wrong answer instead of a container kill.
__device__ __forceinline__ void grid_barrier(unsigned NC) {
    __syncthreads();
    if (threadIdx.x == 0) {
        if (!g_bar_broken) {
            __threadfence();
            unsigned e = g_bar_epoch;
            if (atomicAdd(&g_bar_cnt, 1u) == NC - 1u) {
                g_bar_cnt = 0u;
                __threadfence();
                g_bar_epoch = e + 1u;
            } else {
                unsigned long long t0 = clock64();
                while (g_bar_epoch == e && !g_bar_broken) {
                    __nanosleep(32);
                    if (clock64() - t0 > 400000000ULL) { g_bar_broken = 1u; break; }
                }
            }
            __threadfence();
        }
    }
    __syncthreads();
}

// ---------------- GRU recurrence: persistent split-K column scan ----------------
// One launch per layer. CTA owns 8 hidden columns; Wh slices live in SMEM all
// scan. Thread (warp j, lane l) owns output (column c0+j, batch l): its h and z
// stay in registers. Dot products are split-K: warp w processes k2-slice
// [w*K2W,(w+1)*K2W) for ALL 8 columns (h read once per CTA per k2 instead of
// 8x), partials reduced through SMEM (reusing hbuf, sync-guarded).
template <int H>
__global__ void __launch_bounds__(256, 1) gru_scan_kernel(
    const float* __restrict__ Wh,   // [3H, H] rows: r, z, n
    const float* __restrict__ h0,   // [H]
    int NC, int ysel)
{
    extern __shared__ float smem[];
    constexpr int H2  = H / 2;
    constexpr int K2W = H2 / 8;      // k2 iterations per warp
    constexpr int NPT = H / 32;      // float4 staging elems per thread
    float* wA   = smem;              // [H2][8 cols][4]: (Wr2k,Wr2k+1,Wz2k,Wz2k+1)
    float* wN   = wA + H * 16;       // [H2][8 cols][2]: (Wn2k,Wn2k+1)
    float* hbuf = wN + H * 8;        // [H2][32][2]: staged h / r*h; also partial scratch

    const int tid = threadIdx.x;
    const int w   = tid >> 5;        // warp id: K-slice owner AND owned column
    const int l   = tid & 31;        // lane = batch element
    const int c0  = blockIdx.x * 8;
    const int c   = c0 + w;          // owned output column

    if (tid == 0) g_bar_broken = 0;

    // Stage weights once for the whole scan.
    for (int j = 0; j < 8; ++j) {
        const float* wr = Wh + (size_t)(c0 + j) * H;
        const float* wz = Wh + (size_t)(H + c0 + j) * H;
        const float* wn = Wh + (size_t)(2 * H + c0 + j) * H;
        for (int k2 = tid; k2 < H2; k2 += 256) {
            wA[k2 * 32 + j * 4 + 0] = wr[2 * k2];
            wA[k2 * 32 + j * 4 + 1] = wr[2 * k2 + 1];
            wA[k2 * 32 + j * 4 + 2] = wz[2 * k2];
            wA[k2 * 32 + j * 4 + 3] = wz[2 * k2 + 1];
            wN[k2 * 16 + j * 2 + 0] = wn[2 * k2];
            wN[k2 * 16 + j * 2 + 1] = wn[2 * k2 + 1];
        }
    }

    float hval = h0[c];                                    // own h, lives in a register
    __stcg(&g_h[(c >> 1) * 64 + l * 2 + (c & 1)], hval);
    grid_barrier(NC);

    float* ys = (ysel == 1) ? g_bufB : g_bufA;
    const u64*        hb = (const u64*)hbuf;
    const ulonglong2* wa = (const ulonglong2*)wA;
    u64*              pp = (u64*)hbuf;                     // partial scratch (reuse)
    const int k2base = w * K2W;

    for (int s = 0; s < S_LEN; ++s) {
        // ---- stage full h from L2 (MLP-batched) ----
        {
            const float4* src = (const float4*)g_h;
            float4*       dst = (float4*)hbuf;
            #pragma unroll
            for (int t0 = 0; t0 < NPT; t0 += 8) {
                float4 v[8];
                #pragma unroll
                for (int u = 0; u < 8; ++u) v[u] = __ldcg(src + tid + (t0 + u) * 256);
                #pragma unroll
                for (int u = 0; u < 8; ++u) dst[tid + (t0 + u) * 256] = v[u];
            }
        }
        __syncthreads();

        const int xbase = (l * S_LEN + s) * 3 * H + c;
        float xr = __ldg(&g_xg[xbase]);
        float xz = __ldg(&g_xg[xbase + H]);

        // ---- phase A split-K: partial r,z for all 8 columns over own k-slice ----
        u64 acc[8][2];
        #pragma unroll
        for (int j = 0; j < 8; ++j) { acc[j][0] = 0ULL; acc[j][1] = 0ULL; }
        #pragma unroll 4
        for (int kk = 0; kk < K2W; ++kk) {
            const int k2 = k2base + kk;
            u64 h2 = hb[k2 * 32 + l];            // (h[2k2],h[2k2+1]) for batch l
            #pragma unroll
            for (int j = 0; j < 8; ++j) {
                ulonglong2 wv = wa[k2 * 8 + j];  // 16B broadcast: r-pair, z-pair
                fma2(acc[j][0], h2, wv.x);
                fma2(acc[j][1], h2, wv.y);
            }
        }
        __syncthreads();                         // all h2 reads done before overwrite
        #pragma unroll
        for (int j = 0; j < 8; ++j) {
            pp[((w * 8 + j) * 2 + 0) * 32 + l] = acc[j][0];
            pp[((w * 8 + j) * 2 + 1) * 32 + l] = acc[j][1];
        }
        __syncthreads();
        u64 sR = 0ULL, sZ = 0ULL;
        #pragma unroll
        for (int w2 = 0; w2 < 8; ++w2) {
            add2(sR, sR, pp[((w2 * 8 + w) * 2 + 0) * 32 + l]);
            add2(sZ, sZ, pp[((w2 * 8 + w) * 2 + 1) * 32 + l]);
        }
        float r = 1.0f / (1.0f + expf(-(xr + lo32(sR) + hi32(sR))));
        float z = 1.0f / (1.0f + expf(-(xz + lo32(sZ) + hi32(sZ))));
        __stcg(&g_rh[(c >> 1) * 64 + l * 2 + (c & 1)], r * hval);

        grid_barrier(NC);                        // all r*h published

        // ---- stage full r*h ----
        {
            const float4* src = (const float4*)g_rh;
            float4*       dst = (float4*)hbuf;
            #pragma unroll
            for (int t0 = 0; t0 < NPT; t0 += 8) {
                float4 v[8];
                #pragma unroll
                for (int u = 0; u < 8; ++u) v[u] = __ldcg(src + tid + (t0 + u) * 256);
                #pragma unroll
                for (int u = 0; u < 8; ++u) dst[tid + (t0 + u) * 256] = v[u];
            }
        }
        __syncthreads();

        // ---- phase B split-K: partial n for all 8 columns ----
        float xn = __ldg(&g_xg[xbase + 2 * H]);
        u64 accN[8];
        #pragma unroll
        for (int j = 0; j < 8; ++j) accN[j] = 0ULL;
        const ulonglong2* wnp = (const ulonglong2*)wN;
        #pragma unroll 4
        for (int kk = 0; kk < K2W; ++kk) {
            const int k2 = k2base + kk;
            u64 h2 = hb[k2 * 32 + l];
            #pragma unroll
            for (int j2 = 0; j2 < 4; ++j2) {     // 16B broadcast = 2 columns' n-pairs
                ulonglong2 wv = wnp[k2 * 4 + j2];
                fma2(accN[j2 * 2 + 0], h2, wv.x);
                fma2(accN[j2 * 2 + 1], h2, wv.y);
            }
        }
        __syncthreads();
        #pragma unroll
        for (int j = 0; j < 8; ++j) pp[(w * 8 + j) * 32 + l] = accN[j];
        __syncthreads();
        u64 sN = 0ULL;
        #pragma unroll
        for (int w2 = 0; w2 < 8; ++w2) add2(sN, sN, pp[(w2 * 8 + w) * 32 + l]);

        float n = tanhf(xn + lo32(sN) + hi32(sN));
        float hnew = (1.0f - z) * hval + z * n;  // nonstandard z convention (matches ref)
        hval = hnew;
        __stcg(&g_h[(c >> 1) * 64 + l * 2 + (c & 1)], hnew);
        ys[(size_t)(l * S_LEN + s) * H + c] = hnew;

        grid_barrier(NC);                        // h complete before next staging
    }
}

// ---------------- fp32 GEMM on packed fma.rn.f32x2 ----------------
// C[M,N] = A[M,K] @ W[N,K]^T + bias (+ReLU). 128x128 tile, BK=16, 256 threads,
// 8x8 microtile. A is staged duplicated ((a,a) pairs) so both FMA2 operands
// come straight from SMEM; B staged as natural pairs.
template <bool RELU>
__global__ void __launch_bounds__(256) gemm_kernel(
    const float* __restrict__ Aext, int asel,
    const float* __restrict__ W, const float* __restrict__ bias,
    float* __restrict__ Cext, int csel,
    int M, int N, int K)
{
    const float* A = sel_in(Aext, asel);
    float*       C = sel_out(Cext, csel);

    __shared__ float As[16 * 256];   // [k][2m] duplicated pairs
    __shared__ float Bs[16 * 128];   // [k][n]

    const int tid = threadIdx.x;
    const int m0  = blockIdx.y * 128;
    const int n0  = blockIdx.x * 128;
    const int tym = tid >> 4;        // 0..15 -> 8 rows each
    const int txn = tid & 15;        // 0..15 -> 8 cols each
    const int row = tid >> 1;        // 0..127 tile row for loads
    const int kh  = (tid & 1) * 8;   // k-half for loads

    u64 acc[8][4];
    #pragma unroll
    for (int i = 0; i < 8; ++i)
        #pragma unroll
        for (int j = 0; j < 4; ++j) acc[i][j] = 0ULL;

    const float* Aptr = A + (size_t)(m0 + row) * K + kh;
    const float* Wptr = W + (size_t)(n0 + row) * K + kh;

    for (int k0 = 0; k0 < K; k0 += 16) {
        float4 a0 = *(const float4*)(Aptr + k0);
        float4 a1 = *(const float4*)(Aptr + k0 + 4);
        float4 b0 = *(const float4*)(Wptr + k0);
        float4 b1 = *(const float4*)(Wptr + k0 + 4);
        __syncthreads();             // previous compute done before overwrite
        float va[8] = {a0.x, a0.y, a0.z, a0.w, a1.x, a1.y, a1.z, a1.w};
        float vb[8] = {b0.x, b0.y, b0.z, b0.w, b1.x, b1.y, b1.z, b1.w};
        #pragma unroll
        for (int i = 0; i < 8; ++i) {
            float2 dup = {va[i], va[i]};
            *(float2*)&As[(kh + i) * 256 + 2 * row] = dup;
            Bs[(kh + i) * 128 + row] = vb[i];
        }
        __syncthreads();
        #pragma unroll
        for (int k = 0; k < 16; ++k) {
            const ulonglong2* ap = (const ulonglong2*)&As[k * 256 + tym * 16];
            ulonglong2 a0v = ap[0], a1v = ap[1], a2v = ap[2], a3v = ap[3];
            const ulonglong2* bp = (const ulonglong2*)&Bs[k * 128 + txn * 8];
            ulonglong2 b0v = bp[0], b1v = bp[1];
            u64 aa[8] = {a0v.x, a0v.y, a1v.x, a1v.y, a2v.x, a2v.y, a3v.x, a3v.y};
            u64 bb[4] = {b0v.x, b0v.y, b1v.x, b1v.y};
            #pragma unroll
            for (int i = 0; i < 8; ++i)
                #pragma unroll
                for (int j = 0; j < 4; ++j)
                    fma2(acc[i][j], aa[i], bb[j]);
        }
    }

    const int mBase = m0 + tym * 8;
    const int nBase = n0 + txn * 8;
    #pragma unroll
    for (int i = 0; i < 8; ++i) {
        float* crow = C + (size_t)(mBase + i) * N + nBase;
        #pragma unroll
        for (int j = 0; j < 4; ++j) {
            float v0 = lo32(acc[i][j]) + bias[nBase + 2 * j];
            float v1 = hi32(acc[i][j]) + bias[nBase + 2 * j + 1];
            if (RELU) { v0 = fmaxf(v0, 0.0f); v1 = fmaxf(v1, 0.0f); }
            crow[2 * j]     = v0;
            crow[2 * j + 1] = v1;
        }
    }
}

// ---------------- host ----------------
extern "C" void kernel_launch(void* const* d_in, const int* in_sizes, int n_in,
                              void* d_out, int out_size) {
    (void)in_sizes; (void)n_in; (void)out_size;
    const float* x   = (const float*)d_in[0];
    const float* Wi0 = (const float*)d_in[1];
    const float* Wh0 = (const float*)d_in[2];
    const float* bh0 = (const float*)d_in[3];
    const float* h00 = (const float*)d_in[4];
    const float* Wi1 = (const float*)d_in[5];
    const float* Wh1 = (const float*)d_in[6];
    const float* bh1 = (const float*)d_in[7];
    const float* h01 = (const float*)d_in[8];
    const float* Wi2 = (const float*)d_in[9];
    const float* Wh2 = (const float*)d_in[10];
    const float* bh2 = (const float*)d_in[11];
    const float* h02 = (const float*)d_in[12];
    const float* Wo  = (const float*)d_in[13];
    const float* bo  = (const float*)d_in[14];
    float* out = (float*)d_out;

    // scan SMEM: 56*H floats (wA 16H + wN 8H + hbuf 32H)
    cudaFuncSetAttribute(gru_scan_kernel<512>,
                         cudaFuncAttributeMaxDynamicSharedMemorySize, 56 * 512 * 4);
    cudaFuncSetAttribute(gru_scan_kernel<1024>,
                         cudaFuncAttributeMaxDynamicSharedMemorySize, 56 * 1024 * 4);

    const int M = 16384;
    dim3 blk(256);

    // ---- layer 0: I=256, H=512 ----
    gemm_kernel<false><<<dim3(12, 128), blk>>>(x, 3, Wi0, bh0, nullptr, 2, M, 1536, 256);
    gru_scan_kernel<512><<<64, blk, 56 * 512 * 4>>>(Wh0, h00, 64, 0);
    // ---- layer 1: I=512, H=1024 ----
    gemm_kernel<false><<<dim3(24, 128), blk>>>(nullptr, 0, Wi1, bh1, nullptr, 2, M, 3072, 512);
    gru_scan_kernel<1024><<<128, blk, 56 * 1024 * 4>>>(Wh1, h01, 128, 1);
    // ---- layer 2: I=1024, H=512 ----
    gemm_kernel<false><<<dim3(12, 128), blk>>>(nullptr, 1, Wi2, bh2, nullptr, 2, M, 1536, 1024);
    gru_scan_kernel<512><<<64, blk, 56 * 512 * 4>>>(Wh2, h02, 64, 0);
    // ---- output head: [16384,512] @ Wo^T -> [16384,256], ReLU ----
    gemm_kernel<true><<<dim3(2, 128), blk>>>(nullptr, 0, Wo, bo, out, 3, M, 256, 512);
}

// round 9
// speedup vs baseline: 1.3443x; 1.0562x over previous
#include <cuda_runtime.h>
#include <math.h>
#include <stdint.h>

#define S_LEN 512

typedef unsigned long long u64;

__device__ __forceinline__ void fma2(u64 &d, u64 a, u64 b) {
    asm("fma.rn.f32x2 %0, %1, %2, %3;" : "=l"(d) : "l"(a), "l"(b), "l"(d));
}
__device__ __forceinline__ void add2(u64 &d, u64 a, u64 b) {
    asm("add.rn.f32x2 %0, %1, %2;" : "=l"(d) : "l"(a), "l"(b));
}
__device__ __forceinline__ u64 dup2(float a) {
    u64 d; asm("mov.b64 %0, {%1, %1};" : "=l"(d) : "f"(a)); return d;
}
__device__ __forceinline__ float lo32(u64 v) { return __uint_as_float((unsigned)(v & 0xffffffffULL)); }
__device__ __forceinline__ float hi32(u64 v) { return __uint_as_float((unsigned)(v >> 32)); }

// ---------------- static scratch (no allocations allowed) ----------------
__device__ float g_xg  [16384 * 3072];  // input-projection output, reused per layer
__device__ float g_bufA[16384 * 512];   // layer0 out, later layer2 out
__device__ float g_bufB[16384 * 1024];  // layer1 out
__device__ float g_h   [32 * 1024];     // hidden state, packed [k/2][b][2]
__device__ float g_rh  [32 * 1024];     // r*h, same packing

__device__ unsigned          g_bar_cnt    = 0;
__device__ volatile unsigned g_bar_epoch  = 0;
__device__ volatile unsigned g_bar_broken = 0;

__device__ __forceinline__ const float* sel_in(const float* ext, int sel) {
    return sel == 0 ? g_bufA : (sel == 1 ? g_bufB : ext);
}
__device__ __forceinline__ float* sel_out(float* ext, int sel) {
    return sel == 0 ? g_bufA : (sel == 1 ? g_bufB : (sel == 2 ? g_xg : ext));
}

// Software grid barrier — byte-identical to the rounds-6/7 validated version.
// All NC CTAs co-resident (SMEM forces 1 CTA/SM, NC <= 128 <= 148 SMs).
// Escape hatch: a waiter spinning > ~0.2s marks the barrier broken; later
// barriers fall through -> fast wrong answer instead of a container kill.
__device__ __forceinline__ void grid_barrier(unsigned NC) {
    __syncthreads();
    if (threadIdx.x == 0) {
        if (!g_bar_broken) {
            __threadfence();
            unsigned e = g_bar_epoch;
            if (atomicAdd(&g_bar_cnt, 1u) == NC - 1u) {
                g_bar_cnt = 0u;
                __threadfence();
                g_bar_epoch = e + 1u;
            } else {
                unsigned long long t0 = clock64();
                while (g_bar_epoch == e && !g_bar_broken) {
                    __nanosleep(32);
                    if (clock64() - t0 > 400000000ULL) { g_bar_broken = 1u; break; }
                }
            }
            __threadfence();
        }
    }
    __syncthreads();
}

// ---------------- GRU recurrence: persistent split-K column scan ----------------
// Structure identical to round 7 (validated). Only change: x-gate loads hoisted
// above the h staging so their ~600cyc scattered-load latency overlaps staging.
template <int H>
__global__ void __launch_bounds__(256, 1) gru_scan_kernel(
    const float* __restrict__ Wh,   // [3H, H] rows: r, z, n
    const float* __restrict__ h0,   // [H]
    int NC, int ysel)
{
    extern __shared__ float smem[];
    constexpr int H2  = H / 2;
    constexpr int K2W = H2 / 8;      // k2 iterations per warp
    constexpr int NPT = H / 32;      // float4 staging elems per thread
    float* wA   = smem;              // [H2][8 cols][4]: (Wr2k,Wr2k+1,Wz2k,Wz2k+1)
    float* wN   = wA + H * 16;       // [H2][8 cols][2]: (Wn2k,Wn2k+1)
    float* hbuf = wN + H * 8;        // [H2][32][2]: staged h / r*h; partial scratch

    const int tid = threadIdx.x;
    const int w   = tid >> 5;        // warp id: K-slice owner AND owned column
    const int l   = tid & 31;        // lane = batch element
    const int c0  = blockIdx.x * 8;
    const int c   = c0 + w;          // owned output column

    if (tid == 0) g_bar_broken = 0;

    // Stage weights once for the whole scan.
    for (int j = 0; j < 8; ++j) {
        const float* wr = Wh + (size_t)(c0 + j) * H;
        const float* wz = Wh + (size_t)(H + c0 + j) * H;
        const float* wn = Wh + (size_t)(2 * H + c0 + j) * H;
        for (int k2 = tid; k2 < H2; k2 += 256) {
            wA[k2 * 32 + j * 4 + 0] = wr[2 * k2];
            wA[k2 * 32 + j * 4 + 1] = wr[2 * k2 + 1];
            wA[k2 * 32 + j * 4 + 2] = wz[2 * k2];
            wA[k2 * 32 + j * 4 + 3] = wz[2 * k2 + 1];
            wN[k2 * 16 + j * 2 + 0] = wn[2 * k2];
            wN[k2 * 16 + j * 2 + 1] = wn[2 * k2 + 1];
        }
    }

    float hval = h0[c];                                    // own h, lives in a register
    __stcg(&g_h[(c >> 1) * 64 + l * 2 + (c & 1)], hval);
    grid_barrier(NC);

    float* ys = (ysel == 1) ? g_bufB : g_bufA;
    const u64*        hb  = (const u64*)hbuf;
    const ulonglong2* wa  = (const ulonglong2*)wA;
    const ulonglong2* wnp = (const ulonglong2*)wN;
    u64*              pp  = (u64*)hbuf;                    // partial scratch (reuse)
    const int k2base = w * K2W;

    for (int s = 0; s < S_LEN; ++s) {
        // x-gate loads first: scattered L2/DRAM misses overlap the staging below
        const int xbase = (l * S_LEN + s) * 3 * H + c;
        float xr = __ldg(&g_xg[xbase]);
        float xz = __ldg(&g_xg[xbase + H]);
        float xn = __ldg(&g_xg[xbase + 2 * H]);

        // ---- stage full h from L2 (MLP-batched) ----
        {
            const float4* src = (const float4*)g_h;
            float4*       dst = (float4*)hbuf;
            #pragma unroll
            for (int t0 = 0; t0 < NPT; t0 += 8) {
                float4 v[8];
                #pragma unroll
                for (int u = 0; u < 8; ++u) v[u] = __ldcg(src + tid + (t0 + u) * 256);
                #pragma unroll
                for (int u = 0; u < 8; ++u) dst[tid + (t0 + u) * 256] = v[u];
            }
        }
        __syncthreads();

        // ---- phase A split-K: partial r,z for all 8 columns over own k-slice ----
        u64 acc[8][2];
        #pragma unroll
        for (int j = 0; j < 8; ++j) { acc[j][0] = 0ULL; acc[j][1] = 0ULL; }
        #pragma unroll 4
        for (int kk = 0; kk < K2W; ++kk) {
            const int k2 = k2base + kk;
            u64 h2 = hb[k2 * 32 + l];            // (h[2k2],h[2k2+1]) for batch l
            #pragma unroll
            for (int j = 0; j < 8; ++j) {
                ulonglong2 wv = wa[k2 * 8 + j];  // 16B broadcast: r-pair, z-pair
                fma2(acc[j][0], h2, wv.x);
                fma2(acc[j][1], h2, wv.y);
            }
        }
        __syncthreads();                         // all h2 reads done before overwrite
        #pragma unroll
        for (int j = 0; j < 8; ++j) {
            pp[((w * 8 + j) * 2 + 0) * 32 + l] = acc[j][0];
            pp[((w * 8 + j) * 2 + 1) * 32 + l] = acc[j][1];
        }
        __syncthreads();
        u64 sR = 0ULL, sZ = 0ULL;
        #pragma unroll
        for (int w2 = 0; w2 < 8; ++w2) {
            add2(sR, sR, pp[((w2 * 8 + w) * 2 + 0) * 32 + l]);
            add2(sZ, sZ, pp[((w2 * 8 + w) * 2 + 1) * 32 + l]);
        }
        float r = 1.0f / (1.0f + expf(-(xr + lo32(sR) + hi32(sR))));
        float z = 1.0f / (1.0f + expf(-(xz + lo32(sZ) + hi32(sZ))));
        __stcg(&g_rh[(c >> 1) * 64 + l * 2 + (c & 1)], r * hval);

        grid_barrier(NC);                        // all r*h published

        // ---- stage full r*h ----
        {
            const float4* src = (const float4*)g_rh;
            float4*       dst = (float4*)hbuf;
            #pragma unroll
            for (int t0 = 0; t0 < NPT; t0 += 8) {
                float4 v[8];
                #pragma unroll
                for (int u = 0; u < 8; ++u) v[u] = __ldcg(src + tid + (t0 + u) * 256);
                #pragma unroll
                for (int u = 0; u < 8; ++u) dst[tid + (t0 + u) * 256] = v[u];
            }
        }
        __syncthreads();

        // ---- phase B split-K: partial n for all 8 columns ----
        u64 accN[8];
        #pragma unroll
        for (int j = 0; j < 8; ++j) accN[j] = 0ULL;
        #pragma unroll 4
        for (int kk = 0; kk < K2W; ++kk) {
            const int k2 = k2base + kk;
            u64 h2 = hb[k2 * 32 + l];
            #pragma unroll
            for (int j2 = 0; j2 < 4; ++j2) {     // 16B broadcast = 2 columns' n-pairs
                ulonglong2 wv = wnp[k2 * 4 + j2];
                fma2(accN[j2 * 2 + 0], h2, wv.x);
                fma2(accN[j2 * 2 + 1], h2, wv.y);
            }
        }
        __syncthreads();
        #pragma unroll
        for (int j = 0; j < 8; ++j) pp[(w * 8 + j) * 32 + l] = accN[j];
        __syncthreads();
        u64 sN = 0ULL;
        #pragma unroll
        for (int w2 = 0; w2 < 8; ++w2) add2(sN, sN, pp[(w2 * 8 + w) * 32 + l]);

        float n = tanhf(xn + lo32(sN) + hi32(sN));
        float hnew = (1.0f - z) * hval + z * n;  // nonstandard z convention (matches ref)
        hval = hnew;
        __stcg(&g_h[(c >> 1) * 64 + l * 2 + (c & 1)], hnew);
        ys[(size_t)(l * S_LEN + s) * H + c] = hnew;

        grid_barrier(NC);                        // h complete before next staging
    }
}

// ---------------- fp32 GEMM on packed fma.rn.f32x2 ----------------
// C[M,N] = A[M,K] @ W[N,K]^T + bias (+ReLU). 128x128 tile, BK=16, 256 threads,
// 8x8 microtile. A pairs duplicated in REGISTERS (mov.b64 {a,a}) so SMEM holds
// plain tiles: 4x LDS.128 per thread per k (64B) vs round 7's 96B.
template <bool RELU>
__global__ void __launch_bounds__(256) gemm_kernel(
    const float* __restrict__ Aext, int asel,
    const float* __restrict__ W, const float* __restrict__ bias,
    float* __restrict__ Cext, int csel,
    int M, int N, int K)
{
    const float* A = sel_in(Aext, asel);
    float*       C = sel_out(Cext, csel);

    __shared__ float As[16][128];   // [k][m]
    __shared__ float Bs[16][128];   // [k][n]

    const int tid = threadIdx.x;
    const int m0  = blockIdx.y * 128;
    const int n0  = blockIdx.x * 128;
    const int tym = tid >> 4;        // 0..15 -> 8 rows each
    const int txn = tid & 15;        // 0..15 -> 8 cols each
    const int row = tid >> 1;        // 0..127 tile row for loads
    const int kh  = (tid & 1) * 8;   // k-half for loads

    u64 acc[8][4];
    #pragma unroll
    for (int i = 0; i < 8; ++i)
        #pragma unroll
        for (int j = 0; j < 4; ++j) acc[i][j] = 0ULL;

    const float* Aptr = A + (size_t)(m0 + row) * K + kh;
    const float* Wptr = W + (size_t)(n0 + row) * K + kh;

    for (int k0 = 0; k0 < K; k0 += 16) {
        float4 a0 = *(const float4*)(Aptr + k0);
        float4 a1 = *(const float4*)(Aptr + k0 + 4);
        float4 b0 = *(const float4*)(Wptr + k0);
        float4 b1 = *(const float4*)(Wptr + k0 + 4);
        __syncthreads();             // previous compute done before overwrite
        float va[8] = {a0.x, a0.y, a0.z, a0.w, a1.x, a1.y, a1.z, a1.w};
        float vb[8] = {b0.x, b0.y, b0.z, b0.w, b1.x, b1.y, b1.z, b1.w};
        #pragma unroll
        for (int i = 0; i < 8; ++i) {
            As[kh + i][row] = va[i];
            Bs[kh + i][row] = vb[i];
        }
        __syncthreads();
        #pragma unroll
        for (int k = 0; k < 16; ++k) {
            float4 af0 = *(const float4*)&As[k][tym * 8];
            float4 af1 = *(const float4*)&As[k][tym * 8 + 4];
            const ulonglong2* bp = (const ulonglong2*)&Bs[k][txn * 8];
            ulonglong2 b0v = bp[0], b1v = bp[1];
            u64 aa[8] = {dup2(af0.x), dup2(af0.y), dup2(af0.z), dup2(af0.w),
                         dup2(af1.x), dup2(af1.y), dup2(af1.z), dup2(af1.w)};
            u64 bb[4] = {b0v.x, b0v.y, b1v.x, b1v.y};
            #pragma unroll
            for (int i = 0; i < 8; ++i)
                #pragma unroll
                for (int j = 0; j < 4; ++j)
                    fma2(acc[i][j], aa[i], bb[j]);
        }
    }

    const int mBase = m0 + tym * 8;
    const int nBase = n0 + txn * 8;
    #pragma unroll
    for (int i = 0; i < 8; ++i) {
        float* crow = C + (size_t)(mBase + i) * N + nBase;
        #pragma unroll
        for (int j = 0; j < 4; ++j) {
            float v0 = lo32(acc[i][j]) + bias[nBase + 2 * j];
            float v1 = hi32(acc[i][j]) + bias[nBase + 2 * j + 1];
            if (RELU) { v0 = fmaxf(v0, 0.0f); v1 = fmaxf(v1, 0.0f); }
            crow[2 * j]     = v0;
            crow[2 * j + 1] = v1;
        }
    }
}

// ---------------- host ----------------
extern "C" void kernel_launch(void* const* d_in, const int* in_sizes, int n_in,
                              void* d_out, int out_size) {
    (void)in_sizes; (void)n_in; (void)out_size;
    const float* x   = (const float*)d_in[0];
    const float* Wi0 = (const float*)d_in[1];
    const float* Wh0 = (const float*)d_in[2];
    const float* bh0 = (const float*)d_in[3];
    const float* h00 = (const float*)d_in[4];
    const float* Wi1 = (const float*)d_in[5];
    const float* Wh1 = (const float*)d_in[6];
    const float* bh1 = (const float*)d_in[7];
    const float* h01 = (const float*)d_in[8];
    const float* Wi2 = (const float*)d_in[9];
    const float* Wh2 = (const float*)d_in[10];
    const float* bh2 = (const float*)d_in[11];
    const float* h02 = (const float*)d_in[12];
    const float* Wo  = (const float*)d_in[13];
    const float* bo  = (const float*)d_in[14];
    float* out = (float*)d_out;

    // scan SMEM: 56*H floats (wA 16H + wN 8H + hbuf 32H)
    cudaFuncSetAttribute(gru_scan_kernel<512>,
                         cudaFuncAttributeMaxDynamicSharedMemorySize, 56 * 512 * 4);
    cudaFuncSetAttribute(gru_scan_kernel<1024>,
                         cudaFuncAttributeMaxDynamicSharedMemorySize, 56 * 1024 * 4);

    const int M = 16384;
    dim3 blk(256);

    // ---- layer 0: I=256, H=512 ----
    gemm_kernel<false><<<dim3(12, 128), blk>>>(x, 3, Wi0, bh0, nullptr, 2, M, 1536, 256);
    gru_scan_kernel<512><<<64, blk, 56 * 512 * 4>>>(Wh0, h00, 64, 0);
    // ---- layer 1: I=512, H=1024 ----
    gemm_kernel<false><<<dim3(24, 128), blk>>>(nullptr, 0, Wi1, bh1, nullptr, 2, M, 3072, 512);
    gru_scan_kernel<1024><<<128, blk, 56 * 1024 * 4>>>(Wh1, h01, 128, 1);
    // ---- layer 2: I=1024, H=512 ----
    gemm_kernel<false><<<dim3(12, 128), blk>>>(nullptr, 1, Wi2, bh2, nullptr, 2, M, 1536, 1024);
    gru_scan_kernel<512><<<64, blk, 56 * 512 * 4>>>(Wh2, h02, 64, 0);
    // ---- output head: [16384,512] @ Wo^T -> [16384,256], ReLU ----
    gemm_kernel<true><<<dim3(2, 128), blk>>>(nullptr, 0, Wo, bo, out, 3, M, 256, 512);
}

// round 11
// speedup vs baseline: 1.4603x; 1.0863x over previous
#include <cuda_runtime.h>
#include <math.h>
#include <stdint.h>

#define S_LEN 512

typedef unsigned long long u64;

__device__ __forceinline__ void fma2(u64 &d, u64 a, u64 b) {
    asm("fma.rn.f32x2 %0, %1, %2, %3;" : "=l"(d) : "l"(a), "l"(b), "l"(d));
}
__device__ __forceinline__ void add2(u64 &d, u64 a, u64 b) {
    asm("add.rn.f32x2 %0, %1, %2;" : "=l"(d) : "l"(a), "l"(b));
}
__device__ __forceinline__ u64 dup2(float a) {
    u64 d; asm("mov.b64 %0, {%1, %1};" : "=l"(d) : "f"(a)); return d;
}
__device__ __forceinline__ float lo32(u64 v) { return __uint_as_float((unsigned)(v & 0xffffffffULL)); }
__device__ __forceinline__ float hi32(u64 v) { return __uint_as_float((unsigned)(v >> 32)); }

// ---------------- static scratch (no allocations allowed) ----------------
__device__ float g_xg  [16384 * 3072];  // input-projection output, reused per layer
__device__ float g_bufA[16384 * 512];   // layer0 out, later layer2 out
__device__ float g_bufB[16384 * 1024];  // layer1 out
__device__ float g_h   [32 * 1024];     // hidden state, packed [k/2][b][2]
__device__ float g_rh  [32 * 1024];     // r*h, same packing

// Flag-array barrier state: one monotonic flag per CTA, 128B apart.
// Single writer per word, never reset -> reset races are impossible.
__device__ volatile unsigned g_flags[128 * 32];
__device__ volatile unsigned g_bar_broken = 0;

__device__ __forceinline__ const float* sel_in(const float* ext, int sel) {
    return sel == 0 ? g_bufA : (sel == 1 ? g_bufB : ext);
}
__device__ __forceinline__ float* sel_out(float* ext, int sel) {
    return sel == 0 ? g_bufA : (sel == 1 ? g_bufB : (sel == 2 ? g_xg : ext));
}

// Flag-array grid barrier. Arrival = ONE volatile store of (my_base + bar_k)
// to this CTA's own flag (no atomics, no arrival serialization). Wait =
// threads tid<NC poll one flag each in parallel until it has advanced bar_k
// past the base recorded at launch start (unsigned-wrap-safe compare), then
// __syncthreads. All NC CTAs co-resident (SMEM forces 1 CTA/SM, NC<=128<=148).
// Escape hatch: poll > ~0.2s sets g_bar_broken; all barriers fall through ->
// fast wrong answer (visible rel_err) instead of a container kill.
__device__ __forceinline__ void flag_barrier(int tid, int bid, int NC,
                                             unsigned my_base, unsigned watch_base,
                                             unsigned &bar_k) {
    __syncthreads();                      // all CTA work for this phase done
    bar_k++;
    if (tid == 0) {
        __threadfence();                  // publish data before the flag
        g_flags[bid * 32] = my_base + bar_k;
    }
    if (tid < NC && !g_bar_broken) {
        unsigned long long t0 = 0;
        int it = 0;
        while ((unsigned)(g_flags[tid * 32] - watch_base) < bar_k) {
            if (g_bar_broken) break;
            if ((++it & 2047) == 0) {
                if (t0 == 0) t0 = clock64();
                else if (clock64() - t0 > 400000000ULL) { g_bar_broken = 1u; break; }
            }
        }
    }
    __threadfence();                      // acquire: order staging loads after polls
    __syncthreads();
}

// ---------------- GRU recurrence: persistent split-K column scan ----------------
// Compute structure byte-identical to round 9 (validated). 256 threads,
// 8 warps: warp w = K-slice owner AND owner of column c0+w.
template <int H>
__global__ void __launch_bounds__(256, 1) gru_scan_kernel(
    const float* __restrict__ Wh,   // [3H, H] rows: r, z, n
    const float* __restrict__ h0,   // [H]
    int NC, int ysel)
{
    extern __shared__ float smem[];
    constexpr int H2  = H / 2;
    constexpr int K2W = H2 / 8;      // k2 iterations per warp
    constexpr int NPT = H / 32;      // float4 staging elems per thread
    float* wA   = smem;              // [H2][8 cols][4]: (Wr2k,Wr2k+1,Wz2k,Wz2k+1)
    float* wN   = wA + H * 16;       // [H2][8 cols][2]: (Wn2k,Wn2k+1)
    float* hbuf = wN + H * 8;        // [H2][32][2]: staged h / r*h; partial scratch

    const int tid = threadIdx.x;
    const int w   = tid >> 5;        // warp id: K-slice owner AND owned column
    const int l   = tid & 31;        // lane = batch element
    const int bid = blockIdx.x;
    const int c0  = bid * 8;
    const int c   = c0 + w;          // owned output column

    // Barrier bases: flags persist across launches/replays and are monotonic;
    // re-reading them here makes every launch self-consistent (also across the
    // 64-CTA and 128-CTA grids, whose flags advance by different amounts).
    const unsigned my_base    = g_flags[bid * 32];
    const unsigned watch_base = (tid < NC) ? g_flags[tid * 32] : 0u;
    unsigned bar_k = 0;
    if (tid == 0) g_bar_broken = 0;  // benign pre-barrier multi-writer reset

    // Stage weights once for the whole scan.
    for (int j = 0; j < 8; ++j) {
        const float* wr = Wh + (size_t)(c0 + j) * H;
        const float* wz = Wh + (size_t)(H + c0 + j) * H;
        const float* wn = Wh + (size_t)(2 * H + c0 + j) * H;
        for (int k2 = tid; k2 < H2; k2 += 256) {
            wA[k2 * 32 + j * 4 + 0] = wr[2 * k2];
            wA[k2 * 32 + j * 4 + 1] = wr[2 * k2 + 1];
            wA[k2 * 32 + j * 4 + 2] = wz[2 * k2];
            wA[k2 * 32 + j * 4 + 3] = wz[2 * k2 + 1];
            wN[k2 * 16 + j * 2 + 0] = wn[2 * k2];
            wN[k2 * 16 + j * 2 + 1] = wn[2 * k2 + 1];
        }
    }

    float hval = h0[c];                                    // own h, lives in a register
    __stcg(&g_h[(c >> 1) * 64 + l * 2 + (c & 1)], hval);
    flag_barrier(tid, bid, NC, my_base, watch_base, bar_k);

    float* ys = (ysel == 1) ? g_bufB : g_bufA;
    const u64*        hb  = (const u64*)hbuf;
    const ulonglong2* wa  = (const ulonglong2*)wA;
    const ulonglong2* wnp = (const ulonglong2*)wN;
    u64*              pp  = (u64*)hbuf;                    // partial scratch (reuse)
    const int k2base = w * K2W;

    for (int s = 0; s < S_LEN; ++s) {
        // x-gate loads first: scattered L2/DRAM misses overlap the staging below
        const int xbase = (l * S_LEN + s) * 3 * H + c;
        float xr = __ldg(&g_xg[xbase]);
        float xz = __ldg(&g_xg[xbase + H]);
        float xn = __ldg(&g_xg[xbase + 2 * H]);

        // ---- stage full h from L2 (MLP-batched) ----
        {
            const float4* src = (const float4*)g_h;
            float4*       dst = (float4*)hbuf;
            #pragma unroll
            for (int t0 = 0; t0 < NPT; t0 += 8) {
                float4 v[8];
                #pragma unroll
                for (int u = 0; u < 8; ++u) v[u] = __ldcg(src + tid + (t0 + u) * 256);
                #pragma unroll
                for (int u = 0; u < 8; ++u) dst[tid + (t0 + u) * 256] = v[u];
            }
        }
        __syncthreads();

        // ---- phase A split-K: partial r,z for all 8 columns over own k-slice ----
        u64 acc[8][2];
        #pragma unroll
        for (int j = 0; j < 8; ++j) { acc[j][0] = 0ULL; acc[j][1] = 0ULL; }
        #pragma unroll 4
        for (int kk = 0; kk < K2W; ++kk) {
            const int k2 = k2base + kk;
            u64 h2 = hb[k2 * 32 + l];            // (h[2k2],h[2k2+1]) for batch l
            #pragma unroll
            for (int j = 0; j < 8; ++j) {
                ulonglong2 wv = wa[k2 * 8 + j];  // 16B broadcast: r-pair, z-pair
                fma2(acc[j][0], h2, wv.x);
                fma2(acc[j][1], h2, wv.y);
            }
        }
        __syncthreads();                         // all h2 reads done before overwrite
        #pragma unroll
        for (int j = 0; j < 8; ++j) {
            pp[((w * 8 + j) * 2 + 0) * 32 + l] = acc[j][0];
            pp[((w * 8 + j) * 2 + 1) * 32 + l] = acc[j][1];
        }
        __syncthreads();
        u64 sR = 0ULL, sZ = 0ULL;
        #pragma unroll
        for (int w2 = 0; w2 < 8; ++w2) {
            add2(sR, sR, pp[((w2 * 8 + w) * 2 + 0) * 32 + l]);
            add2(sZ, sZ, pp[((w2 * 8 + w) * 2 + 1) * 32 + l]);
        }
        float r = 1.0f / (1.0f + expf(-(xr + lo32(sR) + hi32(sR))));
        float z = 1.0f / (1.0f + expf(-(xz + lo32(sZ) + hi32(sZ))));
        __stcg(&g_rh[(c >> 1) * 64 + l * 2 + (c & 1)], r * hval);

        flag_barrier(tid, bid, NC, my_base, watch_base, bar_k);  // all r*h published

        // ---- stage full r*h ----
        {
            const float4* src = (const float4*)g_rh;
            float4*       dst = (float4*)hbuf;
            #pragma unroll
            for (int t0 = 0; t0 < NPT; t0 += 8) {
                float4 v[8];
                #pragma unroll
                for (int u = 0; u < 8; ++u) v[u] = __ldcg(src + tid + (t0 + u) * 256);
                #pragma unroll
                for (int u = 0; u < 8; ++u) dst[tid + (t0 + u) * 256] = v[u];
            }
        }
        __syncthreads();

        // ---- phase B split-K: partial n for all 8 columns ----
        u64 accN[8];
        #pragma unroll
        for (int j = 0; j < 8; ++j) accN[j] = 0ULL;
        #pragma unroll 4
        for (int kk = 0; kk < K2W; ++kk) {
            const int k2 = k2base + kk;
            u64 h2 = hb[k2 * 32 + l];
            #pragma unroll
            for (int j2 = 0; j2 < 4; ++j2) {     // 16B broadcast = 2 columns' n-pairs
                ulonglong2 wv = wnp[k2 * 4 + j2];
                fma2(accN[j2 * 2 + 0], h2, wv.x);
                fma2(accN[j2 * 2 + 1], h2, wv.y);
            }
        }
        __syncthreads();
        #pragma unroll
        for (int j = 0; j < 8; ++j) pp[(w * 8 + j) * 32 + l] = accN[j];
        __syncthreads();
        u64 sN = 0ULL;
        #pragma unroll
        for (int w2 = 0; w2 < 8; ++w2) add2(sN, sN, pp[(w2 * 8 + w) * 32 + l]);

        float n = tanhf(xn + lo32(sN) + hi32(sN));
        float hnew = (1.0f - z) * hval + z * n;  // nonstandard z convention (matches ref)
        hval = hnew;
        __stcg(&g_h[(c >> 1) * 64 + l * 2 + (c & 1)], hnew);
        ys[(size_t)(l * S_LEN + s) * H + c] = hnew;

        flag_barrier(tid, bid, NC, my_base, watch_base, bar_k);  // h complete
    }
}

// ---------------- fp32 GEMM on packed fma.rn.f32x2 ----------------
// Byte-identical to the round-9 validated version (register-duplicated A).
template <bool RELU>
__global__ void __launch_bounds__(256) gemm_kernel(
    const float* __restrict__ Aext, int asel,
    const float* __restrict__ W, const float* __restrict__ bias,
    float* __restrict__ Cext, int csel,
    int M, int N, int K)
{
    const float* A = sel_in(Aext, asel);
    float*       C = sel_out(Cext, csel);

    __shared__ float As[16][128];   // [k][m]
    __shared__ float Bs[16][128];   // [k][n]

    const int tid = threadIdx.x;
    const int m0  = blockIdx.y * 128;
    const int n0  = blockIdx.x * 128;
    const int tym = tid >> 4;        // 0..15 -> 8 rows each
    const int txn = tid & 15;        // 0..15 -> 8 cols each
    const int row = tid >> 1;        // 0..127 tile row for loads
    const int kh  = (tid & 1) * 8;   // k-half for loads

    u64 acc[8][4];
    #pragma unroll
    for (int i = 0; i < 8; ++i)
        #pragma unroll
        for (int j = 0; j < 4; ++j) acc[i][j] = 0ULL;

    const float* Aptr = A + (size_t)(m0 + row) * K + kh;
    const float* Wptr = W + (size_t)(n0 + row) * K + kh;

    for (int k0 = 0; k0 < K; k0 += 16) {
        float4 a0 = *(const float4*)(Aptr + k0);
        float4 a1 = *(const float4*)(Aptr + k0 + 4);
        float4 b0 = *(const float4*)(Wptr + k0);
        float4 b1 = *(const float4*)(Wptr + k0 + 4);
        __syncthreads();             // previous compute done before overwrite
        float va[8] = {a0.x, a0.y, a0.z, a0.w, a1.x, a1.y, a1.z, a1.w};
        float vb[8] = {b0.x, b0.y, b0.z, b0.w, b1.x, b1.y, b1.z, b1.w};
        #pragma unroll
        for (int i = 0; i < 8; ++i) {
            As[kh + i][row] = va[i];
            Bs[kh + i][row] = vb[i];
        }
        __syncthreads();
        #pragma unroll
        for (int k = 0; k < 16; ++k) {
            float4 af0 = *(const float4*)&As[k][tym * 8];
            float4 af1 = *(const float4*)&As[k][tym * 8 + 4];
            const ulonglong2* bp = (const ulonglong2*)&Bs[k][txn * 8];
            ulonglong2 b0v = bp[0], b1v = bp[1];
            u64 aa[8] = {dup2(af0.x), dup2(af0.y), dup2(af0.z), dup2(af0.w),
                         dup2(af1.x), dup2(af1.y), dup2(af1.z), dup2(af1.w)};
            u64 bb[4] = {b0v.x, b0v.y, b1v.x, b1v.y};
            #pragma unroll
            for (int i = 0; i < 8; ++i)
                #pragma unroll
                for (int j = 0; j < 4; ++j)
                    fma2(acc[i][j], aa[i], bb[j]);
        }
    }

    const int mBase = m0 + tym * 8;
    const int nBase = n0 + txn * 8;
    #pragma unroll
    for (int i = 0; i < 8; ++i) {
        float* crow = C + (size_t)(mBase + i) * N + nBase;
        #pragma unroll
        for (int j = 0; j < 4; ++j) {
            float v0 = lo32(acc[i][j]) + bias[nBase + 2 * j];
            float v1 = hi32(acc[i][j]) + bias[nBase + 2 * j + 1];
            if (RELU) { v0 = fmaxf(v0, 0.0f); v1 = fmaxf(v1, 0.0f); }
            crow[2 * j]     = v0;
            crow[2 * j + 1] = v1;
        }
    }
}

// ---------------- host ----------------
extern "C" void kernel_launch(void* const* d_in, const int* in_sizes, int n_in,
                              void* d_out, int out_size) {
    (void)in_sizes; (void)n_in; (void)out_size;
    const float* x   = (const float*)d_in[0];
    const float* Wi0 = (const float*)d_in[1];
    const float* Wh0 = (const float*)d_in[2];
    const float* bh0 = (const float*)d_in[3];
    const float* h00 = (const float*)d_in[4];
    const float* Wi1 = (const float*)d_in[5];
    const float* Wh1 = (const float*)d_in[6];
    const float* bh1 = (const float*)d_in[7];
    const float* h01 = (const float*)d_in[8];
    const float* Wi2 = (const float*)d_in[9];
    const float* Wh2 = (const float*)d_in[10];
    const float* bh2 = (const float*)d_in[11];
    const float* h02 = (const float*)d_in[12];
    const float* Wo  = (const float*)d_in[13];
    const float* bo  = (const float*)d_in[14];
    float* out = (float*)d_out;

    // scan SMEM: 56*H floats (wA 16H + wN 8H + hbuf 32H)
    cudaFuncSetAttribute(gru_scan_kernel<512>,
                         cudaFuncAttributeMaxDynamicSharedMemorySize, 56 * 512 * 4);
    cudaFuncSetAttribute(gru_scan_kernel<1024>,
                         cudaFuncAttributeMaxDynamicSharedMemorySize, 56 * 1024 * 4);

    const int M = 16384;
    dim3 blk(256);

    // ---- layer 0: I=256, H=512 ----
    gemm_kernel<false><<<dim3(12, 128), blk>>>(x, 3, Wi0, bh0, nullptr, 2, M, 1536, 256);
    gru_scan_kernel<512><<<64, blk, 56 * 512 * 4>>>(Wh0, h00, 64, 0);
    // ---- layer 1: I=512, H=1024 ----
    gemm_kernel<false><<<dim3(24, 128), blk>>>(nullptr, 0, Wi1, bh1, nullptr, 2, M, 3072, 512);
    gru_scan_kernel<1024><<<128, blk, 56 * 1024 * 4>>>(Wh1, h01, 128, 1);
    // ---- layer 2: I=1024, H=512 ----
    gemm_kernel<false><<<dim3(12, 128), blk>>>(nullptr, 1, Wi2, bh2, nullptr, 2, M, 1536, 1024);
    gru_scan_kernel<512><<<64, blk, 56 * 512 * 4>>>(Wh2, h02, 64, 0);
    // ---- output head: [16384,512] @ Wo^T -> [16384,256], ReLU ----
    gemm_kernel<true><<<dim3(2, 128), blk>>>(nullptr, 0, Wo, bo, out, 3, M, 256, 512);
}

// round 12
// speedup vs baseline: 1.5955x; 1.0926x over previous
#include <cuda_runtime.h>
#include <math.h>
#include <stdint.h>

#define S_LEN 512

typedef unsigned long long u64;

__device__ __forceinline__ void fma2(u64 &d, u64 a, u64 b) {
    asm("fma.rn.f32x2 %0, %1, %2, %3;" : "=l"(d) : "l"(a), "l"(b), "l"(d));
}
__device__ __forceinline__ void add2(u64 &d, u64 a, u64 b) {
    asm("add.rn.f32x2 %0, %1, %2;" : "=l"(d) : "l"(a), "l"(b));
}
__device__ __forceinline__ u64 dup2(float a) {
    u64 d; asm("mov.b64 %0, {%1, %1};" : "=l"(d) : "f"(a)); return d;
}
__device__ __forceinline__ float lo32(u64 v) { return __uint_as_float((unsigned)(v & 0xffffffffULL)); }
__device__ __forceinline__ float hi32(u64 v) { return __uint_as_float((unsigned)(v >> 32)); }
__device__ __forceinline__ u64 ldcg64(const u64* p) {
    u64 v; asm volatile("ld.global.cg.b64 %0, [%1];" : "=l"(v) : "l"(p)); return v;
}

// ---------------- static scratch (no allocations allowed) ----------------
__device__ float g_xg  [16384 * 3072];  // input-projection output, reused per layer
__device__ float g_bufA[16384 * 512];   // layer0 out, later layer2 out
__device__ float g_bufB[16384 * 1024];  // layer1 out
__device__ float g_h   [32 * 1024];     // hidden state, packed [k/2][b][2]
__device__ float g_rh  [32 * 1024];     // r*h, same packing

// Flag-array barrier state: one monotonic flag per CTA, 128B apart.
// Single writer per word, never reset -> reset races are impossible.
__device__ volatile unsigned g_flags[128 * 32];
__device__ volatile unsigned g_bar_broken = 0;

__device__ __forceinline__ const float* sel_in(const float* ext, int sel) {
    return sel == 0 ? g_bufA : (sel == 1 ? g_bufB : ext);
}
__device__ __forceinline__ float* sel_out(float* ext, int sel) {
    return sel == 0 ? g_bufA : (sel == 1 ? g_bufB : (sel == 2 ? g_xg : ext));
}

// Flag-array grid barrier — byte-identical to the round-11 validated version.
__device__ __forceinline__ void flag_barrier(int tid, int bid, int NC,
                                             unsigned my_base, unsigned watch_base,
                                             unsigned &bar_k) {
    __syncthreads();                      // all CTA work for this phase done
    bar_k++;
    if (tid == 0) {
        __threadfence();                  // publish data before the flag
        g_flags[bid * 32] = my_base + bar_k;
    }
    if (tid < NC && !g_bar_broken) {
        unsigned long long t0 = 0;
        int it = 0;
        while ((unsigned)(g_flags[tid * 32] - watch_base) < bar_k) {
            if (g_bar_broken) break;
            if ((++it & 2047) == 0) {
                if (t0 == 0) t0 = clock64();
                else if (clock64() - t0 > 400000000ULL) { g_bar_broken = 1u; break; }
            }
        }
    }
    __threadfence();                      // acquire: order h/rh loads after polls
    __syncthreads();
}

// ---------------- GRU recurrence: persistent split-K column scan ----------------
// Round-11 structure with ONE change: NO SMEM staging of h/rh. A warp's h2
// access hb[k2*32+l] is 256B-contiguous per k2 — identical to g_h's own
// layout — so phase A/B load h2 directly from L2 with coalesced ld.global.cg
// u64 loads, MLP-batched 8 deep to hide ~240cyc L2 latency under compute.
// This deletes both staging loops, 3 CTA syncs per step, and all h2 LDS
// traffic. pp gets a dedicated SMEM region (no aliasing).
template <int H>
__global__ void __launch_bounds__(256, 1) gru_scan_kernel(
    const float* __restrict__ Wh,   // [3H, H] rows: r, z, n
    const float* __restrict__ h0,   // [H]
    int NC, int ysel)
{
    extern __shared__ float smem[];
    constexpr int H2  = H / 2;
    constexpr int K2W = H2 / 8;      // k2 iterations per warp
    float* wA = smem;                // [H2][8 cols][4]: (Wr2k,Wr2k+1,Wz2k,Wz2k+1)
    float* wN = wA + H * 16;         // [H2][8 cols][2]: (Wn2k,Wn2k+1)
    u64*   pp = (u64*)(wN + H * 8);  // [128][32] u64 partial scratch (32KB)

    const int tid = threadIdx.x;
    const int w   = tid >> 5;        // warp id: K-slice owner AND owned column
    const int l   = tid & 31;        // lane = batch element
    const int bid = blockIdx.x;
    const int c0  = bid * 8;
    const int c   = c0 + w;          // owned output column

    // Barrier bases (flags are monotonic and persist across launches/replays).
    const unsigned my_base    = g_flags[bid * 32];
    const unsigned watch_base = (tid < NC) ? g_flags[tid * 32] : 0u;
    unsigned bar_k = 0;
    if (tid == 0) g_bar_broken = 0;  // benign pre-barrier multi-writer reset

    // Stage weights once for the whole scan.
    for (int j = 0; j < 8; ++j) {
        const float* wr = Wh + (size_t)(c0 + j) * H;
        const float* wz = Wh + (size_t)(H + c0 + j) * H;
        const float* wn = Wh + (size_t)(2 * H + c0 + j) * H;
        for (int k2 = tid; k2 < H2; k2 += 256) {
            wA[k2 * 32 + j * 4 + 0] = wr[2 * k2];
            wA[k2 * 32 + j * 4 + 1] = wr[2 * k2 + 1];
            wA[k2 * 32 + j * 4 + 2] = wz[2 * k2];
            wA[k2 * 32 + j * 4 + 3] = wz[2 * k2 + 1];
            wN[k2 * 16 + j * 2 + 0] = wn[2 * k2];
            wN[k2 * 16 + j * 2 + 1] = wn[2 * k2 + 1];
        }
    }

    float hval = h0[c];                                    // own h, lives in a register
    __stcg(&g_h[(c >> 1) * 64 + l * 2 + (c & 1)], hval);
    flag_barrier(tid, bid, NC, my_base, watch_base, bar_k);

    float* ys = (ysel == 1) ? g_bufB : g_bufA;
    const u64*        gh  = (const u64*)g_h;
    const u64*        grh = (const u64*)g_rh;
    const ulonglong2* wa  = (const ulonglong2*)wA;
    const ulonglong2* wnp = (const ulonglong2*)wN;
    const int k2base = w * K2W;

    for (int s = 0; s < S_LEN; ++s) {
        const int xbase = (l * S_LEN + s) * 3 * H + c;
        float xr = __ldg(&g_xg[xbase]);
        float xz = __ldg(&g_xg[xbase + H]);
        float xn = __ldg(&g_xg[xbase + 2 * H]);

        // ---- phase A split-K: partial r,z for all 8 columns over own k-slice ----
        // h2 loaded straight from L2, 8 loads in flight per group (MLP=8).
        u64 acc[8][2];
        #pragma unroll
        for (int j = 0; j < 8; ++j) { acc[j][0] = 0ULL; acc[j][1] = 0ULL; }
        for (int kk = 0; kk < K2W; kk += 8) {
            u64 h2v[8];
            #pragma unroll
            for (int u = 0; u < 8; ++u)
                h2v[u] = ldcg64(gh + (k2base + kk + u) * 32 + l);
            #pragma unroll
            for (int u = 0; u < 8; ++u) {
                const int k2 = k2base + kk + u;
                #pragma unroll
                for (int j = 0; j < 8; ++j) {
                    ulonglong2 wv = wa[k2 * 8 + j];  // 16B broadcast: r-pair, z-pair
                    fma2(acc[j][0], h2v[u], wv.x);
                    fma2(acc[j][1], h2v[u], wv.y);
                }
            }
        }
        #pragma unroll
        for (int j = 0; j < 8; ++j) {
            pp[((w * 8 + j) * 2 + 0) * 32 + l] = acc[j][0];
            pp[((w * 8 + j) * 2 + 1) * 32 + l] = acc[j][1];
        }
        __syncthreads();
        u64 sR = 0ULL, sZ = 0ULL;
        #pragma unroll
        for (int w2 = 0; w2 < 8; ++w2) {
            add2(sR, sR, pp[((w2 * 8 + w) * 2 + 0) * 32 + l]);
            add2(sZ, sZ, pp[((w2 * 8 + w) * 2 + 1) * 32 + l]);
        }
        float r = 1.0f / (1.0f + expf(-(xr + lo32(sR) + hi32(sR))));
        float z = 1.0f / (1.0f + expf(-(xz + lo32(sZ) + hi32(sZ))));
        __stcg(&g_rh[(c >> 1) * 64 + l * 2 + (c & 1)], r * hval);

        flag_barrier(tid, bid, NC, my_base, watch_base, bar_k);  // all r*h published

        // ---- phase B split-K: partial n for all 8 columns ----
        u64 accN[8];
        #pragma unroll
        for (int j = 0; j < 8; ++j) accN[j] = 0ULL;
        for (int kk = 0; kk < K2W; kk += 8) {
            u64 h2v[8];
            #pragma unroll
            for (int u = 0; u < 8; ++u)
                h2v[u] = ldcg64(grh + (k2base + kk + u) * 32 + l);
            #pragma unroll
            for (int u = 0; u < 8; ++u) {
                const int k2 = k2base + kk + u;
                #pragma unroll
                for (int j2 = 0; j2 < 4; ++j2) {     // 16B broadcast = 2 columns' n-pairs
                    ulonglong2 wv = wnp[k2 * 4 + j2];
                    fma2(accN[j2 * 2 + 0], h2v[u], wv.x);
                    fma2(accN[j2 * 2 + 1], h2v[u], wv.y);
                }
            }
        }
        __syncthreads();                 // reduction reads of phase A done (pp reuse)
        #pragma unroll
        for (int j = 0; j < 8; ++j) pp[(w * 8 + j) * 32 + l] = accN[j];
        __syncthreads();
        u64 sN = 0ULL;
        #pragma unroll
        for (int w2 = 0; w2 < 8; ++w2) add2(sN, sN, pp[(w2 * 8 + w) * 32 + l]);

        float n = tanhf(xn + lo32(sN) + hi32(sN));
        float hnew = (1.0f - z) * hval + z * n;  // nonstandard z convention (matches ref)
        hval = hnew;
        __stcg(&g_h[(c >> 1) * 64 + l * 2 + (c & 1)], hnew);
        ys[(size_t)(l * S_LEN + s) * H + c] = hnew;

        flag_barrier(tid, bid, NC, my_base, watch_base, bar_k);  // h complete
    }
}

// ---------------- fp32 GEMM on packed fma.rn.f32x2 ----------------
// Byte-identical to the rounds-9/11 validated version (register-duplicated A).
template <bool RELU>
__global__ void __launch_bounds__(256) gemm_kernel(
    const float* __restrict__ Aext, int asel,
    const float* __restrict__ W, const float* __restrict__ bias,
    float* __restrict__ Cext, int csel,
    int M, int N, int K)
{
    const float* A = sel_in(Aext, asel);
    float*       C = sel_out(Cext, csel);

    __shared__ float As[16][128];   // [k][m]
    __shared__ float Bs[16][128];   // [k][n]

    const int tid = threadIdx.x;
    const int m0  = blockIdx.y * 128;
    const int n0  = blockIdx.x * 128;
    const int tym = tid >> 4;        // 0..15 -> 8 rows each
    const int txn = tid & 15;        // 0..15 -> 8 cols each
    const int row = tid >> 1;        // 0..127 tile row for loads
    const int kh  = (tid & 1) * 8;   // k-half for loads

    u64 acc[8][4];
    #pragma unroll
    for (int i = 0; i < 8; ++i)
        #pragma unroll
        for (int j = 0; j < 4; ++j) acc[i][j] = 0ULL;

    const float* Aptr = A + (size_t)(m0 + row) * K + kh;
    const float* Wptr = W + (size_t)(n0 + row) * K + kh;

    for (int k0 = 0; k0 < K; k0 += 16) {
        float4 a0 = *(const float4*)(Aptr + k0);
        float4 a1 = *(const float4*)(Aptr + k0 + 4);
        float4 b0 = *(const float4*)(Wptr + k0);
        float4 b1 = *(const float4*)(Wptr + k0 + 4);
        __syncthreads();             // previous compute done before overwrite
        float va[8] = {a0.x, a0.y, a0.z, a0.w, a1.x, a1.y, a1.z, a1.w};
        float vb[8] = {b0.x, b0.y, b0.z, b0.w, b1.x, b1.y, b1.z, b1.w};
        #pragma unroll
        for (int i = 0; i < 8; ++i) {
            As[kh + i][row] = va[i];
            Bs[kh + i][row] = vb[i];
        }
        __syncthreads();
        #pragma unroll
        for (int k = 0; k < 16; ++k) {
            float4 af0 = *(const float4*)&As[k][tym * 8];
            float4 af1 = *(const float4*)&As[k][tym * 8 + 4];
            const ulonglong2* bp = (const ulonglong2*)&Bs[k][txn * 8];
            ulonglong2 b0v = bp[0], b1v = bp[1];
            u64 aa[8] = {dup2(af0.x), dup2(af0.y), dup2(af0.z), dup2(af0.w),
                         dup2(af1.x), dup2(af1.y), dup2(af1.z), dup2(af1.w)};
            u64 bb[4] = {b0v.x, b0v.y, b1v.x, b1v.y};
            #pragma unroll
            for (int i = 0; i < 8; ++i)
                #pragma unroll
                for (int j = 0; j < 4; ++j)
                    fma2(acc[i][j], aa[i], bb[j]);
        }
    }

    const int mBase = m0 + tym * 8;
    const int nBase = n0 + txn * 8;
    #pragma unroll
    for (int i = 0; i < 8; ++i) {
        float* crow = C + (size_t)(mBase + i) * N + nBase;
        #pragma unroll
        for (int j = 0; j < 4; ++j) {
            float v0 = lo32(acc[i][j]) + bias[nBase + 2 * j];
            float v1 = hi32(acc[i][j]) + bias[nBase + 2 * j + 1];
            if (RELU) { v0 = fmaxf(v0, 0.0f); v1 = fmaxf(v1, 0.0f); }
            crow[2 * j]     = v0;
            crow[2 * j + 1] = v1;
        }
    }
}

// ---------------- host ----------------
extern "C" void kernel_launch(void* const* d_in, const int* in_sizes, int n_in,
                              void* d_out, int out_size) {
    (void)in_sizes; (void)n_in; (void)out_size;
    const float* x   = (const float*)d_in[0];
    const float* Wi0 = (const float*)d_in[1];
    const float* Wh0 = (const float*)d_in[2];
    const float* bh0 = (const float*)d_in[3];
    const float* h00 = (const float*)d_in[4];
    const float* Wi1 = (const float*)d_in[5];
    const float* Wh1 = (const float*)d_in[6];
    const float* bh1 = (const float*)d_in[7];
    const float* h01 = (const float*)d_in[8];
    const float* Wi2 = (const float*)d_in[9];
    const float* Wh2 = (const float*)d_in[10];
    const float* bh2 = (const float*)d_in[11];
    const float* h02 = (const float*)d_in[12];
    const float* Wo  = (const float*)d_in[13];
    const float* bo  = (const float*)d_in[14];
    float* out = (float*)d_out;

    // scan SMEM: weights 24H floats + 32KB pp. H=1024 -> 128KB; H=512 -> 80KB,
    // padded to 120KB so 1 CTA/SM (co-residency for the grid barrier) holds.
    const int sm512  = 122880;
    const int sm1024 = 24 * 1024 * 4 + 32768;   // 131072
    cudaFuncSetAttribute(gru_scan_kernel<512>,
                         cudaFuncAttributeMaxDynamicSharedMemorySize, sm512);
    cudaFuncSetAttribute(gru_scan_kernel<1024>,
                         cudaFuncAttributeMaxDynamicSharedMemorySize, sm1024);

    const int M = 16384;
    dim3 blk(256);

    // ---- layer 0: I=256, H=512 ----
    gemm_kernel<false><<<dim3(12, 128), blk>>>(x, 3, Wi0, bh0, nullptr, 2, M, 1536, 256);
    gru_scan_kernel<512><<<64, blk, sm512>>>(Wh0, h00, 64, 0);
    // ---- layer 1: I=512, H=1024 ----
    gemm_kernel<false><<<dim3(24, 128), blk>>>(nullptr, 0, Wi1, bh1, nullptr, 2, M, 3072, 512);
    gru_scan_kernel<1024><<<128, blk, sm1024>>>(Wh1, h01, 128, 1);
    // ---- layer 2: I=1024, H=512 ----
    gemm_kernel<false><<<dim3(12, 128), blk>>>(nullptr, 1, Wi2, bh2, nullptr, 2, M, 1536, 1024);
    gru_scan_kernel<512><<<64, blk, sm512>>>(Wh2, h02, 64, 0);
    // ---- output head: [16384,512] @ Wo^T -> [16384,256], ReLU ----
    gemm_kernel<true><<<dim3(2, 128), blk>>>(nullptr, 0, Wo, bo, out, 3, M, 256, 512);
}

// round 13
// speedup vs baseline: 1.5998x; 1.0027x over previous
#include <cuda_runtime.h>
#include <math.h>
#include <stdint.h>

#define S_LEN 512

typedef unsigned long long u64;

__device__ __forceinline__ void fma2(u64 &d, u64 a, u64 b) {
    asm("fma.rn.f32x2 %0, %1, %2, %3;" : "=l"(d) : "l"(a), "l"(b), "l"(d));
}
__device__ __forceinline__ void add2(u64 &d, u64 a, u64 b) {
    asm("add.rn.f32x2 %0, %1, %2;" : "=l"(d) : "l"(a), "l"(b));
}
__device__ __forceinline__ u64 dup2(float a) {
    u64 d; asm("mov.b64 %0, {%1, %1};" : "=l"(d) : "f"(a)); return d;
}
__device__ __forceinline__ float lo32(u64 v) { return __uint_as_float((unsigned)(v & 0xffffffffULL)); }
__device__ __forceinline__ float hi32(u64 v) { return __uint_as_float((unsigned)(v >> 32)); }
__device__ __forceinline__ u64 ldcg64(const u64* p) {
    u64 v; asm volatile("ld.global.cg.b64 %0, [%1];" : "=l"(v) : "l"(p)); return v;
}

// ---------------- static scratch (no allocations allowed) ----------------
__device__ float g_xg  [16384 * 3072];  // input-projection output, reused per layer
__device__ float g_bufA[16384 * 512];   // layer0 out, later layer2 out
__device__ float g_bufB[16384 * 1024];  // layer1 out
__device__ float g_h   [32 * 1024];     // hidden state, packed [k/2][b][2]
__device__ float g_rh  [32 * 1024];     // r*h, same packing

// Flag-array barrier state: one monotonic flag per CTA, 128B apart.
// Single writer per word, never reset -> reset races are impossible.
__device__ volatile unsigned g_flags[128 * 32];
__device__ volatile unsigned g_bar_broken = 0;

__device__ __forceinline__ const float* sel_in(const float* ext, int sel) {
    return sel == 0 ? g_bufA : (sel == 1 ? g_bufB : ext);
}
__device__ __forceinline__ float* sel_out(float* ext, int sel) {
    return sel == 0 ? g_bufA : (sel == 1 ? g_bufB : (sel == 2 ? g_xg : ext));
}

// Flag-array grid barrier — byte-identical to the rounds-11/12 validated version.
__device__ __forceinline__ void flag_barrier(int tid, int bid, int NC,
                                             unsigned my_base, unsigned watch_base,
                                             unsigned &bar_k) {
    __syncthreads();                      // all CTA work for this phase done
    bar_k++;
    if (tid == 0) {
        __threadfence();                  // publish data before the flag
        g_flags[bid * 32] = my_base + bar_k;
    }
    if (tid < NC && !g_bar_broken) {
        unsigned long long t0 = 0;
        int it = 0;
        while ((unsigned)(g_flags[tid * 32] - watch_base) < bar_k) {
            if (g_bar_broken) break;
            if ((++it & 2047) == 0) {
                if (t0 == 0) t0 = clock64();
                else if (clock64() - t0 > 400000000ULL) { g_bar_broken = 1u; break; }
            }
        }
    }
    __threadfence();                      // acquire: order h/rh loads after polls
    __syncthreads();
}

// ---------------- GRU recurrence: persistent split-K column scan ----------------
// Round-12 structure with ONE change: the k-group loops in phases A and B are
// software-pipelined — group g+1's eight h2 values are prefetched into
// registers while group g computes, hiding the ~240cyc L2 latency that was
// previously exposed at the top of every group.
template <int H>
__global__ void __launch_bounds__(256, 1) gru_scan_kernel(
    const float* __restrict__ Wh,   // [3H, H] rows: r, z, n
    const float* __restrict__ h0,   // [H]
    int NC, int ysel)
{
    extern __shared__ float smem[];
    constexpr int H2   = H / 2;
    constexpr int K2W  = H2 / 8;     // k2 iterations per warp
    constexpr int NGRP = K2W / 8;    // 8-k2 groups per warp
    float* wA = smem;                // [H2][8 cols][4]: (Wr2k,Wr2k+1,Wz2k,Wz2k+1)
    float* wN = wA + H * 16;         // [H2][8 cols][2]: (Wn2k,Wn2k+1)
    u64*   pp = (u64*)(wN + H * 8);  // [128][32] u64 partial scratch (32KB)

    const int tid = threadIdx.x;
    const int w   = tid >> 5;        // warp id: K-slice owner AND owned column
    const int l   = tid & 31;        // lane = batch element
    const int bid = blockIdx.x;
    const int c0  = bid * 8;
    const int c   = c0 + w;          // owned output column

    // Barrier bases (flags are monotonic and persist across launches/replays).
    const unsigned my_base    = g_flags[bid * 32];
    const unsigned watch_base = (tid < NC) ? g_flags[tid * 32] : 0u;
    unsigned bar_k = 0;
    if (tid == 0) g_bar_broken = 0;  // benign pre-barrier multi-writer reset

    // Stage weights once for the whole scan.
    for (int j = 0; j < 8; ++j) {
        const float* wr = Wh + (size_t)(c0 + j) * H;
        const float* wz = Wh + (size_t)(H + c0 + j) * H;
        const float* wn = Wh + (size_t)(2 * H + c0 + j) * H;
        for (int k2 = tid; k2 < H2; k2 += 256) {
            wA[k2 * 32 + j * 4 + 0] = wr[2 * k2];
            wA[k2 * 32 + j * 4 + 1] = wr[2 * k2 + 1];
            wA[k2 * 32 + j * 4 + 2] = wz[2 * k2];
            wA[k2 * 32 + j * 4 + 3] = wz[2 * k2 + 1];
            wN[k2 * 16 + j * 2 + 0] = wn[2 * k2];
            wN[k2 * 16 + j * 2 + 1] = wn[2 * k2 + 1];
        }
    }

    float hval = h0[c];                                    // own h, lives in a register
    __stcg(&g_h[(c >> 1) * 64 + l * 2 + (c & 1)], hval);
    flag_barrier(tid, bid, NC, my_base, watch_base, bar_k);

    float* ys = (ysel == 1) ? g_bufB : g_bufA;
    const u64*        gh  = (const u64*)g_h;
    const u64*        grh = (const u64*)g_rh;
    const ulonglong2* wa  = (const ulonglong2*)wA;
    const ulonglong2* wnp = (const ulonglong2*)wN;
    const int k2base = w * K2W;

    for (int s = 0; s < S_LEN; ++s) {
        const int xbase = (l * S_LEN + s) * 3 * H + c;
        float xr = __ldg(&g_xg[xbase]);
        float xz = __ldg(&g_xg[xbase + H]);
        float xn = __ldg(&g_xg[xbase + 2 * H]);

        // ---- phase A split-K: partial r,z for all 8 columns over own k-slice ----
        // Double-buffered: group g+1's h2 prefetched while group g computes.
        u64 acc[8][2];
        #pragma unroll
        for (int j = 0; j < 8; ++j) { acc[j][0] = 0ULL; acc[j][1] = 0ULL; }
        {
            u64 cur[8], nxt[8];
            #pragma unroll
            for (int u = 0; u < 8; ++u)
                cur[u] = ldcg64(gh + (k2base + u) * 32 + l);
            #pragma unroll 2
            for (int g = 0; g < NGRP; ++g) {
                if (g + 1 < NGRP) {
                    #pragma unroll
                    for (int u = 0; u < 8; ++u)
                        nxt[u] = ldcg64(gh + (k2base + (g + 1) * 8 + u) * 32 + l);
                }
                #pragma unroll
                for (int u = 0; u < 8; ++u) {
                    const int k2 = k2base + g * 8 + u;
                    #pragma unroll
                    for (int j = 0; j < 8; ++j) {
                        ulonglong2 wv = wa[k2 * 8 + j];  // 16B broadcast: r-pair, z-pair
                        fma2(acc[j][0], cur[u], wv.x);
                        fma2(acc[j][1], cur[u], wv.y);
                    }
                }
                #pragma unroll
                for (int u = 0; u < 8; ++u) cur[u] = nxt[u];
            }
        }
        #pragma unroll
        for (int j = 0; j < 8; ++j) {
            pp[((w * 8 + j) * 2 + 0) * 32 + l] = acc[j][0];
            pp[((w * 8 + j) * 2 + 1) * 32 + l] = acc[j][1];
        }
        __syncthreads();
        u64 sR = 0ULL, sZ = 0ULL;
        #pragma unroll
        for (int w2 = 0; w2 < 8; ++w2) {
            add2(sR, sR, pp[((w2 * 8 + w) * 2 + 0) * 32 + l]);
            add2(sZ, sZ, pp[((w2 * 8 + w) * 2 + 1) * 32 + l]);
        }
        float r = 1.0f / (1.0f + expf(-(xr + lo32(sR) + hi32(sR))));
        float z = 1.0f / (1.0f + expf(-(xz + lo32(sZ) + hi32(sZ))));
        __stcg(&g_rh[(c >> 1) * 64 + l * 2 + (c & 1)], r * hval);

        flag_barrier(tid, bid, NC, my_base, watch_base, bar_k);  // all r*h published

        // ---- phase B split-K: partial n for all 8 columns (double-buffered) ----
        u64 accN[8];
        #pragma unroll
        for (int j = 0; j < 8; ++j) accN[j] = 0ULL;
        {
            u64 cur[8], nxt[8];
            #pragma unroll
            for (int u = 0; u < 8; ++u)
                cur[u] = ldcg64(grh + (k2base + u) * 32 + l);
            #pragma unroll 2
            for (int g = 0; g < NGRP; ++g) {
                if (g + 1 < NGRP) {
                    #pragma unroll
                    for (int u = 0; u < 8; ++u)
                        nxt[u] = ldcg64(grh + (k2base + (g + 1) * 8 + u) * 32 + l);
                }
                #pragma unroll
                for (int u = 0; u < 8; ++u) {
                    const int k2 = k2base + g * 8 + u;
                    #pragma unroll
                    for (int j2 = 0; j2 < 4; ++j2) {     // 16B = 2 columns' n-pairs
                        ulonglong2 wv = wnp[k2 * 4 + j2];
                        fma2(accN[j2 * 2 + 0], cur[u], wv.x);
                        fma2(accN[j2 * 2 + 1], cur[u], wv.y);
                    }
                }
                #pragma unroll
                for (int u = 0; u < 8; ++u) cur[u] = nxt[u];
            }
        }
        __syncthreads();                 // reduction reads of phase A done (pp reuse)
        #pragma unroll
        for (int j = 0; j < 8; ++j) pp[(w * 8 + j) * 32 + l] = accN[j];
        __syncthreads();
        u64 sN = 0ULL;
        #pragma unroll
        for (int w2 = 0; w2 < 8; ++w2) add2(sN, sN, pp[(w2 * 8 + w) * 32 + l]);

        float n = tanhf(xn + lo32(sN) + hi32(sN));
        float hnew = (1.0f - z) * hval + z * n;  // nonstandard z convention (matches ref)
        hval = hnew;
        __stcg(&g_h[(c >> 1) * 64 + l * 2 + (c & 1)], hnew);
        ys[(size_t)(l * S_LEN + s) * H + c] = hnew;

        flag_barrier(tid, bid, NC, my_base, watch_base, bar_k);  // h complete
    }
}

// ---------------- fp32 GEMM on packed fma.rn.f32x2 ----------------
// Byte-identical to the rounds-9/11/12 validated version (register-duplicated A).
template <bool RELU>
__global__ void __launch_bounds__(256) gemm_kernel(
    const float* __restrict__ Aext, int asel,
    const float* __restrict__ W, const float* __restrict__ bias,
    float* __restrict__ Cext, int csel,
    int M, int N, int K)
{
    const float* A = sel_in(Aext, asel);
    float*       C = sel_out(Cext, csel);

    __shared__ float As[16][128];   // [k][m]
    __shared__ float Bs[16][128];   // [k][n]

    const int tid = threadIdx.x;
    const int m0  = blockIdx.y * 128;
    const int n0  = blockIdx.x * 128;
    const int tym = tid >> 4;        // 0..15 -> 8 rows each
    const int txn = tid & 15;        // 0..15 -> 8 cols each
    const int row = tid >> 1;        // 0..127 tile row for loads
    const int kh  = (tid & 1) * 8;   // k-half for loads

    u64 acc[8][4];
    #pragma unroll
    for (int i = 0; i < 8; ++i)
        #pragma unroll
        for (int j = 0; j < 4; ++j) acc[i][j] = 0ULL;

    const float* Aptr = A + (size_t)(m0 + row) * K + kh;
    const float* Wptr = W + (size_t)(n0 + row) * K + kh;

    for (int k0 = 0; k0 < K; k0 += 16) {
        float4 a0 = *(const float4*)(Aptr + k0);
        float4 a1 = *(const float4*)(Aptr + k0 + 4);
        float4 b0 = *(const float4*)(Wptr + k0);
        float4 b1 = *(const float4*)(Wptr + k0 + 4);
        __syncthreads();             // previous compute done before overwrite
        float va[8] = {a0.x, a0.y, a0.z, a0.w, a1.x, a1.y, a1.z, a1.w};
        float vb[8] = {b0.x, b0.y, b0.z, b0.w, b1.x, b1.y, b1.z, b1.w};
        #pragma unroll
        for (int i = 0; i < 8; ++i) {
            As[kh + i][row] = va[i];
            Bs[kh + i][row] = vb[i];
        }
        __syncthreads();
        #pragma unroll
        for (int k = 0; k < 16; ++k) {
            float4 af0 = *(const float4*)&As[k][tym * 8];
            float4 af1 = *(const float4*)&As[k][tym * 8 + 4];
            const ulonglong2* bp = (const ulonglong2*)&Bs[k][txn * 8];
            ulonglong2 b0v = bp[0], b1v = bp[1];
            u64 aa[8] = {dup2(af0.x), dup2(af0.y), dup2(af0.z), dup2(af0.w),
                         dup2(af1.x), dup2(af1.y), dup2(af1.z), dup2(af1.w)};
            u64 bb[4] = {b0v.x, b0v.y, b1v.x, b1v.y};
            #pragma unroll
            for (int i = 0; i < 8; ++i)
                #pragma unroll
                for (int j = 0; j < 4; ++j)
                    fma2(acc[i][j], aa[i], bb[j]);
        }
    }

    const int mBase = m0 + tym * 8;
    const int nBase = n0 + txn * 8;
    #pragma unroll
    for (int i = 0; i < 8; ++i) {
        float* crow = C + (size_t)(mBase + i) * N + nBase;
        #pragma unroll
        for (int j = 0; j < 4; ++j) {
            float v0 = lo32(acc[i][j]) + bias[nBase + 2 * j];
            float v1 = hi32(acc[i][j]) + bias[nBase + 2 * j + 1];
            if (RELU) { v0 = fmaxf(v0, 0.0f); v1 = fmaxf(v1, 0.0f); }
            crow[2 * j]     = v0;
            crow[2 * j + 1] = v1;
        }
    }
}

// ---------------- host ----------------
extern "C" void kernel_launch(void* const* d_in, const int* in_sizes, int n_in,
                              void* d_out, int out_size) {
    (void)in_sizes; (void)n_in; (void)out_size;
    const float* x   = (const float*)d_in[0];
    const float* Wi0 = (const float*)d_in[1];
    const float* Wh0 = (const float*)d_in[2];
    const float* bh0 = (const float*)d_in[3];
    const float* h00 = (const float*)d_in[4];
    const float* Wi1 = (const float*)d_in[5];
    const float* Wh1 = (const float*)d_in[6];
    const float* bh1 = (const float*)d_in[7];
    const float* h01 = (const float*)d_in[8];
    const float* Wi2 = (const float*)d_in[9];
    const float* Wh2 = (const float*)d_in[10];
    const float* bh2 = (const float*)d_in[11];
    const float* h02 = (const float*)d_in[12];
    const float* Wo  = (const float*)d_in[13];
    const float* bo  = (const float*)d_in[14];
    float* out = (float*)d_out;

    // scan SMEM: weights 24H floats + 32KB pp. H=1024 -> 128KB; H=512 -> 80KB,
    // padded to 120KB so 1 CTA/SM (co-residency for the grid barrier) holds.
    const int sm512  = 122880;
    const int sm1024 = 24 * 1024 * 4 + 32768;   // 131072
    cudaFuncSetAttribute(gru_scan_kernel<512>,
                         cudaFuncAttributeMaxDynamicSharedMemorySize, sm512);
    cudaFuncSetAttribute(gru_scan_kernel<1024>,
                         cudaFuncAttributeMaxDynamicSharedMemorySize, sm1024);

    const int M = 16384;
    dim3 blk(256);

    // ---- layer 0: I=256, H=512 ----
    gemm_kernel<false><<<dim3(12, 128), blk>>>(x, 3, Wi0, bh0, nullptr, 2, M, 1536, 256);
    gru_scan_kernel<512><<<64, blk, sm512>>>(Wh0, h00, 64, 0);
    // ---- layer 1: I=512, H=1024 ----
    gemm_kernel<false><<<dim3(24, 128), blk>>>(nullptr, 0, Wi1, bh1, nullptr, 2, M, 3072, 512);
    gru_scan_kernel<1024><<<128, blk, sm1024>>>(Wh1, h01, 128, 1);
    // ---- layer 2: I=1024, H=512 ----
    gemm_kernel<false><<<dim3(12, 128), blk>>>(nullptr, 1, Wi2, bh2, nullptr, 2, M, 1536, 1024);
    gru_scan_kernel<512><<<64, blk, sm512>>>(Wh2, h02, 64, 0);
    // ---- output head: [16384,512] @ Wo^T -> [16384,256], ReLU ----
    gemm_kernel<true><<<dim3(2, 128), blk>>>(nullptr, 0, Wo, bo, out, 3, M, 256, 512);
}

// round 14
// speedup vs baseline: 1.7699x; 1.1064x over previous
#include <cuda_runtime.h>
#include <math.h>
#include <stdint.h>

#define S_LEN 512

typedef unsigned long long u64;

__device__ __forceinline__ void fma2(u64 &d, u64 a, u64 b) {
    asm("fma.rn.f32x2 %0, %1, %2, %3;" : "=l"(d) : "l"(a), "l"(b), "l"(d));
}
__device__ __forceinline__ void add2(u64 &d, u64 a, u64 b) {
    asm("add.rn.f32x2 %0, %1, %2;" : "=l"(d) : "l"(a), "l"(b));
}
__device__ __forceinline__ u64 dup2(float a) {
    u64 d; asm("mov.b64 %0, {%1, %1};" : "=l"(d) : "f"(a)); return d;
}
__device__ __forceinline__ float lo32(u64 v) { return __uint_as_float((unsigned)(v & 0xffffffffULL)); }
__device__ __forceinline__ float hi32(u64 v) { return __uint_as_float((unsigned)(v >> 32)); }
__device__ __forceinline__ u64 ldcg64(const u64* p) {
    u64 v; asm volatile("ld.global.cg.b64 %0, [%1];" : "=l"(v) : "l"(p)); return v;
}

// ---------------- static scratch (no allocations allowed) ----------------
__device__ float g_xg  [16384 * 3072];  // input-projection output, reused per layer
__device__ float g_bufA[16384 * 512];   // layer0 out, later layer2 out
__device__ float g_bufB[16384 * 1024];  // layer1 out
__device__ float g_h   [32 * 1024];     // hidden state, packed [k/2][b][2]
__device__ float g_rh  [32 * 1024];     // r*h, same packing

// Flag-array barrier state: one monotonic flag per CTA, 128B apart.
// Single writer per word, never reset -> reset races are impossible.
__device__ volatile unsigned g_flags[128 * 32];
__device__ volatile unsigned g_bar_broken = 0;

__device__ __forceinline__ const float* sel_in(const float* ext, int sel) {
    return sel == 0 ? g_bufA : (sel == 1 ? g_bufB : ext);
}
__device__ __forceinline__ float* sel_out(float* ext, int sel) {
    return sel == 0 ? g_bufA : (sel == 1 ? g_bufB : (sel == 2 ? g_xg : ext));
}

// Flag-array grid barrier — byte-identical to the rounds-11/12/13 validated version.
__device__ __forceinline__ void flag_barrier(int tid, int bid, int NC,
                                             unsigned my_base, unsigned watch_base,
                                             unsigned &bar_k) {
    __syncthreads();                      // all CTA work for this phase done
    bar_k++;
    if (tid == 0) {
        __threadfence();                  // publish data before the flag
        g_flags[bid * 32] = my_base + bar_k;
    }
    if (tid < NC && !g_bar_broken) {
        unsigned long long t0 = 0;
        int it = 0;
        while ((unsigned)(g_flags[tid * 32] - watch_base) < bar_k) {
            if (g_bar_broken) break;
            if ((++it & 2047) == 0) {
                if (t0 == 0) t0 = clock64();
                else if (clock64() - t0 > 400000000ULL) { g_bar_broken = 1u; break; }
            }
        }
    }
    __threadfence();                      // acquire: order h/rh loads after polls
    __syncthreads();
}

// ---------------- GRU recurrence: persistent split-K column scan ----------------
// Round-12 structure, generalized over COLS = columns owned per CTA.
// H=1024: COLS=8, 128 CTAs (unchanged). H=512: COLS=4, 128 CTAs — the whole
// chip now works on the small layers (previously 64 CTAs = half idle), halving
// per-SM LDS/FMA per step. Split-K slices (K2W=H2/8 per warp) and the 8-warp
// reduction order are unchanged -> arithmetic bit-identical to round 12.
template <int H, int COLS>
__global__ void __launch_bounds__(256, 1) gru_scan_kernel(
    const float* __restrict__ Wh,   // [3H, H] rows: r, z, n
    const float* __restrict__ h0,   // [H]
    int NC, int ysel)
{
    extern __shared__ float smem[];
    constexpr int H2  = H / 2;
    constexpr int K2W = H2 / 8;            // k2 iterations per warp (8 warps split K)
    float* wA = smem;                      // [H2][COLS][4]: (Wr2k,Wr2k+1,Wz2k,Wz2k+1)
    float* wN = wA + H2 * COLS * 4;        // [H2][COLS][2]: (Wn2k,Wn2k+1)
    u64*   pp = (u64*)(wN + H2 * COLS * 2);// [8*COLS][2][32] u64 partial scratch

    const int tid = threadIdx.x;
    const int w   = tid >> 5;        // warp id: K-slice owner; owns column if w<COLS
    const int l   = tid & 31;        // lane = batch element
    const int bid = blockIdx.x;
    const int c0  = bid * COLS;
    const int c   = c0 + w;          // owned output column (valid for w<COLS)

    // Barrier bases (flags are monotonic and persist across launches/replays).
    const unsigned my_base    = g_flags[bid * 32];
    const unsigned watch_base = (tid < NC) ? g_flags[tid * 32] : 0u;
    unsigned bar_k = 0;
    if (tid == 0) g_bar_broken = 0;  // benign pre-barrier multi-writer reset

    // Stage weights once for the whole scan.
    for (int j = 0; j < COLS; ++j) {
        const float* wr = Wh + (size_t)(c0 + j) * H;
        const float* wz = Wh + (size_t)(H + c0 + j) * H;
        const float* wn = Wh + (size_t)(2 * H + c0 + j) * H;
        for (int k2 = tid; k2 < H2; k2 += 256) {
            wA[k2 * (COLS * 4) + j * 4 + 0] = wr[2 * k2];
            wA[k2 * (COLS * 4) + j * 4 + 1] = wr[2 * k2 + 1];
            wA[k2 * (COLS * 4) + j * 4 + 2] = wz[2 * k2];
            wA[k2 * (COLS * 4) + j * 4 + 3] = wz[2 * k2 + 1];
            wN[k2 * (COLS * 2) + j * 2 + 0] = wn[2 * k2];
            wN[k2 * (COLS * 2) + j * 2 + 1] = wn[2 * k2 + 1];
        }
    }

    float hval = 0.0f;
    if (w < COLS) {
        hval = h0[c];
        __stcg(&g_h[(c >> 1) * 64 + l * 2 + (c & 1)], hval);
    }
    flag_barrier(tid, bid, NC, my_base, watch_base, bar_k);

    float* ys = (ysel == 1) ? g_bufB : g_bufA;
    const u64*        gh  = (const u64*)g_h;
    const u64*        grh = (const u64*)g_rh;
    const ulonglong2* wa  = (const ulonglong2*)wA;
    const ulonglong2* wnp = (const ulonglong2*)wN;
    const int k2base = w * K2W;

    for (int s = 0; s < S_LEN; ++s) {
        const int xbase = (l * S_LEN + s) * 3 * H + c;
        float xr = 0.0f, xz = 0.0f, xn = 0.0f;
        if (w < COLS) {
            xr = __ldg(&g_xg[xbase]);
            xz = __ldg(&g_xg[xbase + H]);
            xn = __ldg(&g_xg[xbase + 2 * H]);
        }

        // ---- phase A split-K: partial r,z for COLS columns over own k-slice ----
        // h2 straight from L2, 8 loads in flight per group (MLP=8).
        u64 acc[COLS][2];
        #pragma unroll
        for (int j = 0; j < COLS; ++j) { acc[j][0] = 0ULL; acc[j][1] = 0ULL; }
        for (int kk = 0; kk < K2W; kk += 8) {
            u64 h2v[8];
            #pragma unroll
            for (int u = 0; u < 8; ++u)
                h2v[u] = ldcg64(gh + (k2base + kk + u) * 32 + l);
            #pragma unroll
            for (int u = 0; u < 8; ++u) {
                const int k2 = k2base + kk + u;
                #pragma unroll
                for (int j = 0; j < COLS; ++j) {
                    ulonglong2 wv = wa[k2 * COLS + j];   // 16B broadcast: r-pair, z-pair
                    fma2(acc[j][0], h2v[u], wv.x);
                    fma2(acc[j][1], h2v[u], wv.y);
                }
            }
        }
        #pragma unroll
        for (int j = 0; j < COLS; ++j) {
            pp[((w * COLS + j) * 2 + 0) * 32 + l] = acc[j][0];
            pp[((w * COLS + j) * 2 + 1) * 32 + l] = acc[j][1];
        }
        __syncthreads();

        float r = 0.0f, z = 0.0f;
        if (w < COLS) {
            u64 sR = 0ULL, sZ = 0ULL;
            #pragma unroll
            for (int w2 = 0; w2 < 8; ++w2) {
                add2(sR, sR, pp[((w2 * COLS + w) * 2 + 0) * 32 + l]);
                add2(sZ, sZ, pp[((w2 * COLS + w) * 2 + 1) * 32 + l]);
            }
            r = 1.0f / (1.0f + expf(-(xr + lo32(sR) + hi32(sR))));
            z = 1.0f / (1.0f + expf(-(xz + lo32(sZ) + hi32(sZ))));
            __stcg(&g_rh[(c >> 1) * 64 + l * 2 + (c & 1)], r * hval);
        }

        flag_barrier(tid, bid, NC, my_base, watch_base, bar_k);  // all r*h published

        // ---- phase B split-K: partial n for COLS columns ----
        u64 accN[COLS];
        #pragma unroll
        for (int j = 0; j < COLS; ++j) accN[j] = 0ULL;
        for (int kk = 0; kk < K2W; kk += 8) {
            u64 h2v[8];
            #pragma unroll
            for (int u = 0; u < 8; ++u)
                h2v[u] = ldcg64(grh + (k2base + kk + u) * 32 + l);
            #pragma unroll
            for (int u = 0; u < 8; ++u) {
                const int k2 = k2base + kk + u;
                #pragma unroll
                for (int j2 = 0; j2 < COLS / 2; ++j2) {  // 16B = 2 columns' n-pairs
                    ulonglong2 wv = wnp[k2 * (COLS / 2) + j2];
                    fma2(accN[j2 * 2 + 0], h2v[u], wv.x);
                    fma2(accN[j2 * 2 + 1], h2v[u], wv.y);
                }
            }
        }
        __syncthreads();                 // reduction reads of phase A done (pp reuse)
        #pragma unroll
        for (int j = 0; j < COLS; ++j) pp[(w * COLS + j) * 32 + l] = accN[j];
        __syncthreads();

        if (w < COLS) {
            u64 sN = 0ULL;
            #pragma unroll
            for (int w2 = 0; w2 < 8; ++w2) add2(sN, sN, pp[(w2 * COLS + w) * 32 + l]);
            float n = tanhf(xn + lo32(sN) + hi32(sN));
            float hnew = (1.0f - z) * hval + z * n;  // nonstandard z convention (matches ref)
            hval = hnew;
            __stcg(&g_h[(c >> 1) * 64 + l * 2 + (c & 1)], hnew);
            ys[(size_t)(l * S_LEN + s) * H + c] = hnew;
        }

        flag_barrier(tid, bid, NC, my_base, watch_base, bar_k);  // h complete
    }
}

// ---------------- fp32 GEMM on packed fma.rn.f32x2 ----------------
// Byte-identical to the rounds-9/11/12/13 validated version (register-dup A).
template <bool RELU>
__global__ void __launch_bounds__(256) gemm_kernel(
    const float* __restrict__ Aext, int asel,
    const float* __restrict__ W, const float* __restrict__ bias,
    float* __restrict__ Cext, int csel,
    int M, int N, int K)
{
    const float* A = sel_in(Aext, asel);
    float*       C = sel_out(Cext, csel);

    __shared__ float As[16][128];   // [k][m]
    __shared__ float Bs[16][128];   // [k][n]

    const int tid = threadIdx.x;
    const int m0  = blockIdx.y * 128;
    const int n0  = blockIdx.x * 128;
    const int tym = tid >> 4;        // 0..15 -> 8 rows each
    const int txn = tid & 15;        // 0..15 -> 8 cols each
    const int row = tid >> 1;        // 0..127 tile row for loads
    const int kh  = (tid & 1) * 8;   // k-half for loads

    u64 acc[8][4];
    #pragma unroll
    for (int i = 0; i < 8; ++i)
        #pragma unroll
        for (int j = 0; j < 4; ++j) acc[i][j] = 0ULL;

    const float* Aptr = A + (size_t)(m0 + row) * K + kh;
    const float* Wptr = W + (size_t)(n0 + row) * K + kh;

    for (int k0 = 0; k0 < K; k0 += 16) {
        float4 a0 = *(const float4*)(Aptr + k0);
        float4 a1 = *(const float4*)(Aptr + k0 + 4);
        float4 b0 = *(const float4*)(Wptr + k0);
        float4 b1 = *(const float4*)(Wptr + k0 + 4);
        __syncthreads();             // previous compute done before overwrite
        float va[8] = {a0.x, a0.y, a0.z, a0.w, a1.x, a1.y, a1.z, a1.w};
        float vb[8] = {b0.x, b0.y, b0.z, b0.w, b1.x, b1.y, b1.z, b1.w};
        #pragma unroll
        for (int i = 0; i < 8; ++i) {
            As[kh + i][row] = va[i];
            Bs[kh + i][row] = vb[i];
        }
        __syncthreads();
        #pragma unroll
        for (int k = 0; k < 16; ++k) {
            float4 af0 = *(const float4*)&As[k][tym * 8];
            float4 af1 = *(const float4*)&As[k][tym * 8 + 4];
            const ulonglong2* bp = (const ulonglong2*)&Bs[k][txn * 8];
            ulonglong2 b0v = bp[0], b1v = bp[1];
            u64 aa[8] = {dup2(af0.x), dup2(af0.y), dup2(af0.z), dup2(af0.w),
                         dup2(af1.x), dup2(af1.y), dup2(af1.z), dup2(af1.w)};
            u64 bb[4] = {b0v.x, b0v.y, b1v.x, b1v.y};
            #pragma unroll
            for (int i = 0; i < 8; ++i)
                #pragma unroll
                for (int j = 0; j < 4; ++j)
                    fma2(acc[i][j], aa[i], bb[j]);
        }
    }

    const int mBase = m0 + tym * 8;
    const int nBase = n0 + txn * 8;
    #pragma unroll
    for (int i = 0; i < 8; ++i) {
        float* crow = C + (size_t)(mBase + i) * N + nBase;
        #pragma unroll
        for (int j = 0; j < 4; ++j) {
            float v0 = lo32(acc[i][j]) + bias[nBase + 2 * j];
            float v1 = hi32(acc[i][j]) + bias[nBase + 2 * j + 1];
            if (RELU) { v0 = fmaxf(v0, 0.0f); v1 = fmaxf(v1, 0.0f); }
            crow[2 * j]     = v0;
            crow[2 * j + 1] = v1;
        }
    }
}

// ---------------- host ----------------
extern "C" void kernel_launch(void* const* d_in, const int* in_sizes, int n_in,
                              void* d_out, int out_size) {
    (void)in_sizes; (void)n_in; (void)out_size;
    const float* x   = (const float*)d_in[0];
    const float* Wi0 = (const float*)d_in[1];
    const float* Wh0 = (const float*)d_in[2];
    const float* bh0 = (const float*)d_in[3];
    const float* h00 = (const float*)d_in[4];
    const float* Wi1 = (const float*)d_in[5];
    const float* Wh1 = (const float*)d_in[6];
    const float* bh1 = (const float*)d_in[7];
    const float* h01 = (const float*)d_in[8];
    const float* Wi2 = (const float*)d_in[9];
    const float* Wh2 = (const float*)d_in[10];
    const float* bh2 = (const float*)d_in[11];
    const float* h02 = (const float*)d_in[12];
    const float* Wo  = (const float*)d_in[13];
    const float* bo  = (const float*)d_in[14];
    float* out = (float*)d_out;

    // scan SMEM: weights (6*H*COLS floats) + pp (8*COLS*2*32*8 B).
    // H=512/COLS=4 needs only 40KB -> padded to 120KB so 1 CTA/SM holds
    // (co-residency invariant for the grid barrier).
    const int sm512  = 122880;                       // padded
    const int sm1024 = 6 * 1024 * 8 * 4 + 32768;     // 131072
    cudaFuncSetAttribute(gru_scan_kernel<512, 4>,
                         cudaFuncAttributeMaxDynamicSharedMemorySize, sm512);
    cudaFuncSetAttribute(gru_scan_kernel<1024, 8>,
                         cudaFuncAttributeMaxDynamicSharedMemorySize, sm1024);

    const int M = 16384;
    dim3 blk(256);

    // ---- layer 0: I=256, H=512 ----
    gemm_kernel<false><<<dim3(12, 128), blk>>>(x, 3, Wi0, bh0, nullptr, 2, M, 1536, 256);
    gru_scan_kernel<512, 4><<<128, blk, sm512>>>(Wh0, h00, 128, 0);
    // ---- layer 1: I=512, H=1024 ----
    gemm_kernel<false><<<dim3(24, 128), blk>>>(nullptr, 0, Wi1, bh1, nullptr, 2, M, 3072, 512);
    gru_scan_kernel<1024, 8><<<128, blk, sm1024>>>(Wh1, h01, 128, 1);
    // ---- layer 2: I=1024, H=512 ----
    gemm_kernel<false><<<dim3(12, 128), blk>>>(nullptr, 1, Wi2, bh2, nullptr, 2, M, 1536, 1024);
    gru_scan_kernel<512, 4><<<128, blk, sm512>>>(Wh2, h02, 128, 0);
    // ---- output head: [16384,512] @ Wo^T -> [16384,256], ReLU ----
    gemm_kernel<true><<<dim3(2, 128), blk>>>(nullptr, 0, Wo, bo, out, 3, M, 256, 512);
}